// round 9
// baseline (speedup 1.0000x reference)
#include <cuda_runtime.h>
#include <cuda_fp16.h>
#include <cstdint>

#define N_NODES 50000
#define NNZ     1600000
#define F       128        // D*B
#define M6      6          // stored matrices: x0,t1,t2,t3,t5,t6
#define M_OUT   7
#define U_DIM   64
#define KSPLIT  24
#define KCH     2112       // 24*2112 = 50688 >= 50000
#define GSTEPS  (KCH / 32) // 66

typedef unsigned int u32;

// ---------------- device scratch (static, no allocation; 16B-aligned for vector casts) ----------------
__device__ __align__(16) __half g_xh[(size_t)M6 * N_NODES * F];       // base matrices in fp16
__device__ __align__(16) __half g_wh[(size_t)N_NODES * F];            // [n][j]: j<64 -> w_ru[:,64+j], j>=64 -> w_c[:,j-64]
__device__ __align__(16) int2   g_csr[2][NNZ];                        // {col, val_bits}
__device__ __align__(16) int    g_rowptr[2][N_NODES + 4];
__device__ __align__(16) int    g_next[2][N_NODES];
__device__ __align__(16) int    g_cnt[2][N_NODES];
__device__ __align__(16) float  g_part[(size_t)KSPLIT * M6 * F * 128];

// ---------------- CSR build ----------------
__global__ void zero2() {
    int i = blockIdx.x * blockDim.x + threadIdx.x;
    if (i < N_NODES) { g_cnt[0][i] = 0; g_cnt[1][i] = 0; }
}

// scalar reads of harness buffers (alignment not guaranteed), 4 edges per thread
__global__ void hist2(const int* __restrict__ lr, const int* __restrict__ rr) {
    int e0 = (blockIdx.x * blockDim.x + threadIdx.x) * 4;
    if (e0 >= NNZ) return;
    int sel = blockIdx.y;
    const int* rows = sel ? rr : lr;
    #pragma unroll
    for (int q = 0; q < 4; q++) {
        atomicAdd(&g_cnt[sel][__ldg(rows + e0 + q)], 1);
    }
}

// one block per sel; exclusive scan of g_cnt[sel] -> g_rowptr[sel] (+ g_next copy)
__global__ void scan2() {
    int sel = blockIdx.x;
    int4* rowptr4 = (int4*)g_rowptr[sel];
    int4* nxt4 = (int4*)g_next[sel];
    const int4* cnt4 = (const int4*)g_cnt[sel];
    __shared__ int warp_sums[32];
    __shared__ int s_carry;
    int tid = threadIdx.x;  // 1024
    if (tid == 0) s_carry = 0;
    __syncthreads();
    const int NQ = N_NODES / 4;  // 12500
    for (int base = 0; base < NQ; base += 1024) {
        int i = base + tid;
        int4 v = (i < NQ) ? cnt4[i] : make_int4(0, 0, 0, 0);
        int s = v.x + v.y + v.z + v.w;
        int x = s;
        #pragma unroll
        for (int o = 1; o < 32; o <<= 1) {
            int y = __shfl_up_sync(0xffffffffu, x, o);
            if ((tid & 31) >= o) x += y;
        }
        if ((tid & 31) == 31) warp_sums[tid >> 5] = x;
        __syncthreads();
        if (tid < 32) {
            int w = warp_sums[tid];
            #pragma unroll
            for (int o = 1; o < 32; o <<= 1) {
                int y = __shfl_up_sync(0xffffffffu, w, o);
                if (tid >= o) w += y;
            }
            warp_sums[tid] = w;
        }
        __syncthreads();
        int warp_off = (tid >= 32) ? warp_sums[(tid >> 5) - 1] : 0;
        int incl = x + warp_off;
        int carry = s_carry;
        if (i < NQ) {
            int p = carry + incl - s;
            int4 o4;
            o4.x = p;
            o4.y = p + v.x;
            o4.z = p + v.x + v.y;
            o4.w = p + v.x + v.y + v.z;
            rowptr4[i] = o4;
            nxt4[i] = o4;
        }
        __syncthreads();
        if (tid == 1023) s_carry = carry + incl;
        __syncthreads();
    }
    if (tid == 0) g_rowptr[sel][N_NODES] = NNZ;
}

// scalar reads; atomic bump cursors; 4 edges per thread
__global__ void scatter2(const int* __restrict__ lr, const int* __restrict__ lc, const float* __restrict__ lv,
                         const int* __restrict__ rr, const int* __restrict__ rc, const float* __restrict__ rv) {
    int e0 = (blockIdx.x * blockDim.x + threadIdx.x) * 4;
    if (e0 >= NNZ) return;
    int sel = blockIdx.y;
    const int* rows = sel ? rr : lr;
    const int* cols = sel ? rc : lc;
    const float* vals = sel ? rv : lv;
    #pragma unroll
    for (int q = 0; q < 4; q++) {
        int e = e0 + q;
        int r = __ldg(rows + e);
        int p = atomicAdd(&g_next[sel][r], 1);
        g_csr[sel][p] = make_int2(__ldg(cols + e), __float_as_int(__ldg(vals + e)));
    }
}

// ---------------- fused prep: x0 transpose + merged fp16 weights ----------------
__global__ void prep(const float* __restrict__ inputs,
                     const float* __restrict__ w_ru, const float* __restrict__ w_c) {
    int idx = blockIdx.x * blockDim.x + threadIdx.x;
    if (idx < N_NODES * 64) {
        int b = idx & 63;
        int n = idx >> 6;
        float vx = __ldg(inputs + ((size_t)b * N_NODES + n) * 2);
        float vy = __ldg(inputs + ((size_t)b * N_NODES + n) * 2 + 1);
        g_xh[(size_t)n * F + b] = __float2half_rn(vx);
        g_xh[(size_t)n * F + 64 + b] = __float2half_rn(vy);
    } else {
        int id2 = idx - N_NODES * 64;
        if (id2 >= N_NODES * F) return;
        int n = id2 >> 7, j = id2 & 127;
        float v = (j < 64) ? __ldg(w_ru + (size_t)n * 128 + 64 + j)
                           : __ldg(w_c + (size_t)n * 64 + (j - 64));
        g_wh[id2] = __float2half_rn(v);
    }
}

// ---------------- SpMM: independent half-warp per row, LDG.128 gathers ----------------
// out = S @ x (raw product only; Chebyshev combines deferred to finish)
__device__ __forceinline__ void spmm_body(int mat, int xi, int oi, int row, int lane) {
    int hl = lane & 15;
    u32 hmask = (lane < 16) ? 0x0000ffffu : 0xffff0000u;
    const uint4* xb = (const uint4*)(g_xh + (size_t)xi * N_NODES * F);
    int e0 = __ldg(&g_rowptr[mat][row]);
    int e1 = __ldg(&g_rowptr[mat][row + 1]);
    float ax = 0.f, ay = 0.f, az = 0.f, aw = 0.f, bx = 0.f, by = 0.f, bz = 0.f, bw = 0.f;
    for (int base = e0; base < e1; base += 16) {
        int n = e1 - base;
        if (n > 16) n = 16;
        int colv = 0; float valv = 0.f;
        if (hl < n) {
            int2 cv = __ldg(&g_csr[mat][base + hl]);
            colv = cv.x << 4;    // uint4 index of gathered row start
            valv = __int_as_float(cv.y);
        }
        int k = 0;
        for (; k + 2 <= n; k += 2) {
            int   c0 = __shfl_sync(hmask, colv, k, 16);
            int   c1 = __shfl_sync(hmask, colv, k + 1, 16);
            float v0 = __shfl_sync(hmask, valv, k, 16);
            float v1 = __shfl_sync(hmask, valv, k + 1, 16);
            uint4 p0 = __ldg(xb + c0 + hl);
            uint4 p1 = __ldg(xb + c1 + hl);
            float2 q0 = __half22float2(*(__half2*)&p0.x);
            float2 q1 = __half22float2(*(__half2*)&p0.y);
            float2 q2 = __half22float2(*(__half2*)&p0.z);
            float2 q3 = __half22float2(*(__half2*)&p0.w);
            ax += v0 * q0.x; ay += v0 * q0.y; az += v0 * q1.x; aw += v0 * q1.y;
            bx += v0 * q2.x; by += v0 * q2.y; bz += v0 * q3.x; bw += v0 * q3.y;
            float2 r0 = __half22float2(*(__half2*)&p1.x);
            float2 r1 = __half22float2(*(__half2*)&p1.y);
            float2 r2 = __half22float2(*(__half2*)&p1.z);
            float2 r3 = __half22float2(*(__half2*)&p1.w);
            ax += v1 * r0.x; ay += v1 * r0.y; az += v1 * r1.x; aw += v1 * r1.y;
            bx += v1 * r2.x; by += v1 * r2.y; bz += v1 * r3.x; bw += v1 * r3.y;
        }
        if (k < n) {
            int   c0 = __shfl_sync(hmask, colv, k, 16);
            float v0 = __shfl_sync(hmask, valv, k, 16);
            uint4 p0 = __ldg(xb + c0 + hl);
            float2 q0 = __half22float2(*(__half2*)&p0.x);
            float2 q1 = __half22float2(*(__half2*)&p0.y);
            float2 q2 = __half22float2(*(__half2*)&p0.z);
            float2 q3 = __half22float2(*(__half2*)&p0.w);
            ax += v0 * q0.x; ay += v0 * q0.y; az += v0 * q1.x; aw += v0 * q1.y;
            bx += v0 * q2.x; by += v0 * q2.y; bz += v0 * q3.x; bw += v0 * q3.y;
        }
    }
    __half2 h0 = __floats2half2_rn(ax, ay);
    __half2 h1 = __floats2half2_rn(az, aw);
    __half2 h2 = __floats2half2_rn(bx, by);
    __half2 h3 = __floats2half2_rn(bz, bw);
    uint4 pk; pk.x = *(u32*)&h0; pk.y = *(u32*)&h1; pk.z = *(u32*)&h2; pk.w = *(u32*)&h3;
    ((uint4*)(g_xh + (size_t)oi * N_NODES * F))[(size_t)row * 16 + hl] = pk;
}

// block = 256 threads = 16 half-warps = 16 rows; grid = 3125 exact
__global__ void __launch_bounds__(256) spmm_w(int mat, int xi, int oi) {
    int lane = threadIdx.x & 31;
    int row = (blockIdx.x << 4) + ((threadIdx.x >> 5) << 1) + (lane >> 4);
    spmm_body(mat, xi, oi, row, lane);
}

// combined: y=0 -> t2 = L t1 ; y=1 -> t3 = R t1
__global__ void __launch_bounds__(256) spmm_dual() {
    int lane = threadIdx.x & 31;
    int row = (blockIdx.x << 4) + ((threadIdx.x >> 5) << 1) + (lane >> 4);
    if (blockIdx.y == 0) spmm_body(0, 1, 2, row, lane);
    else                 spmm_body(1, 1, 3, row, lane);
}

// ---------------- tensor-core GEMM, split-K over 6 base matrices ----------------
__global__ void __launch_bounds__(256) gemm_h() {
    __shared__ __align__(16) __half As[32 * 128];
    __shared__ __align__(16) __half Bs[32 * 128];
    int ks = blockIdx.x, m = blockIdx.y;
    const __half* A = g_xh + (size_t)m * N_NODES * F;
    int tid = threadIdx.x, lane = tid & 31, wid = tid >> 5;
    int f0w = (wid >> 1) * 32;
    int j0w = (wid & 1) * 64;
    u32 as_base = (u32)__cvta_generic_to_shared(As);
    u32 bs_base = (u32)__cvta_generic_to_shared(Bs);

    float c[2][8][4];
    #pragma unroll
    for (int a = 0; a < 2; a++)
        #pragma unroll
        for (int b = 0; b < 8; b++)
            #pragma unroll
            for (int d = 0; d < 4; d++) c[a][b][d] = 0.f;

    int n0 = ks * KCH;
    int lk0 = tid >> 4, lcf = tid & 15;
    int lk1 = lk0 + 16;
    int soff0 = lk0 * 128 + ((lcf ^ (lk0 & 7)) << 3);
    int soff1 = lk1 * 128 + ((lcf ^ (lk1 & 7)) << 3);

    uint4 ra0, ra1, rb0, rb1;
    const uint4 zz = make_uint4(0, 0, 0, 0);
    {
        int na = n0 + lk0, nbg = n0 + lk1;
        if (na < N_NODES) {
            ra0 = *(const uint4*)(A + (size_t)na * F + lcf * 8);
            rb0 = *(const uint4*)(g_wh + (size_t)na * F + lcf * 8);
        } else { ra0 = zz; rb0 = zz; }
        if (nbg < N_NODES) {
            ra1 = *(const uint4*)(A + (size_t)nbg * F + lcf * 8);
            rb1 = *(const uint4*)(g_wh + (size_t)nbg * F + lcf * 8);
        } else { ra1 = zz; rb1 = zz; }
    }

    int g = lane >> 3, i = lane & 7;

    for (int s = 0; s < GSTEPS; s++) {
        __syncthreads();
        *(uint4*)(As + soff0) = ra0; *(uint4*)(Bs + soff0) = rb0;
        *(uint4*)(As + soff1) = ra1; *(uint4*)(Bs + soff1) = rb1;
        __syncthreads();
        if (s + 1 < GSTEPS) {
            int nb = n0 + (s + 1) * 32;
            int na = nb + lk0, nbg = nb + lk1;
            if (na < N_NODES) {
                ra0 = *(const uint4*)(A + (size_t)na * F + lcf * 8);
                rb0 = *(const uint4*)(g_wh + (size_t)na * F + lcf * 8);
            } else { ra0 = zz; rb0 = zz; }
            if (nbg < N_NODES) {
                ra1 = *(const uint4*)(A + (size_t)nbg * F + lcf * 8);
                rb1 = *(const uint4*)(g_wh + (size_t)nbg * F + lcf * 8);
            } else { ra1 = zz; rb1 = zz; }
        }
        #pragma unroll
        for (int kk = 0; kk < 32; kk += 16) {
            u32 a[2][4];
            #pragma unroll
            for (int mt = 0; mt < 2; mt++) {
                int fb = f0w + mt * 16;
                int k = kk + ((g >> 1) << 3) + i;
                int cf = (fb >> 3) + (g & 1);
                u32 addr = as_base + (u32)((k * 128 + ((cf ^ (k & 7)) << 3)) * 2);
                asm volatile("ldmatrix.sync.aligned.m8n8.x4.trans.shared.b16 {%0,%1,%2,%3}, [%4];"
                    : "=r"(a[mt][0]), "=r"(a[mt][1]), "=r"(a[mt][2]), "=r"(a[mt][3]) : "r"(addr));
            }
            u32 b[8][2];
            #pragma unroll
            for (int np = 0; np < 4; np++) {
                int nb = j0w + np * 16;
                int k = kk + ((g & 1) << 3) + i;
                int cf = (nb >> 3) + (g >> 1);
                u32 addr = bs_base + (u32)((k * 128 + ((cf ^ (k & 7)) << 3)) * 2);
                asm volatile("ldmatrix.sync.aligned.m8n8.x4.trans.shared.b16 {%0,%1,%2,%3}, [%4];"
                    : "=r"(b[np * 2][0]), "=r"(b[np * 2][1]), "=r"(b[np * 2 + 1][0]), "=r"(b[np * 2 + 1][1])
                    : "r"(addr));
            }
            #pragma unroll
            for (int mt = 0; mt < 2; mt++)
                #pragma unroll
                for (int nt = 0; nt < 8; nt++)
                    asm volatile("mma.sync.aligned.m16n8k16.row.col.f32.f16.f16.f32 "
                        "{%0,%1,%2,%3}, {%4,%5,%6,%7}, {%8,%9}, {%0,%1,%2,%3};"
                        : "+f"(c[mt][nt][0]), "+f"(c[mt][nt][1]), "+f"(c[mt][nt][2]), "+f"(c[mt][nt][3])
                        : "r"(a[mt][0]), "r"(a[mt][1]), "r"(a[mt][2]), "r"(a[mt][3]),
                          "r"(b[nt][0]), "r"(b[nt][1]));
        }
    }

    float* P = g_part + ((size_t)ks * M6 + m) * F * 128;
    int fr = lane >> 2, jc = (lane & 3) * 2;
    #pragma unroll
    for (int mt = 0; mt < 2; mt++)
        #pragma unroll
        for (int nt = 0; nt < 8; nt++) {
            int f = f0w + mt * 16 + fr;
            int j = j0w + nt * 8 + jc;
            *(float2*)(P + (size_t)f * 128 + j) = make_float2(c[mt][nt][0], c[mt][nt][1]);
            *(float2*)(P + (size_t)(f + 8) * 128 + j) = make_float2(c[mt][nt][2], c[mt][nt][3]);
        }
}

// ---------------- reduce partials + Chebyshev combos + bias + GRU epilogue ----------------
// G_m = sum_ks P[ks][m]; outputs (m=0..6):
//   O0=G0  O1=G1  O2=2G2-G0  O3=G3  O4=2G4-G1  O5=G4  O6=2G5-G3
__global__ void __launch_bounds__(256) finish(const float* __restrict__ hx, const float* __restrict__ b_ru,
                                              const float* __restrict__ b_c, float* __restrict__ out) {
    int idx = blockIdx.x * blockDim.x + threadIdx.x;  // over 128*64 (f, j)
    if (idx >= F * U_DIM) return;
    int j = idx & 63;
    int f = idx >> 6;
    float gu[M6], gc[M6];
    #pragma unroll
    for (int m = 0; m < M6; m++) { gu[m] = 0.f; gc[m] = 0.f; }
    for (int ks = 0; ks < KSPLIT; ks++) {
        const float* Pk = g_part + (size_t)ks * M6 * F * 128 + (size_t)f * 128;
        #pragma unroll
        for (int m = 0; m < M6; m++) {
            gu[m] += Pk[(size_t)m * F * 128 + j];
            gc[m] += Pk[(size_t)m * F * 128 + 64 + j];
        }
    }
    float bu = __ldg(b_ru + 64 + j);
    float bc = __ldg(b_c + j);
    float ou[M_OUT], oc[M_OUT];
    ou[0] = gu[0];                 oc[0] = gc[0];
    ou[1] = gu[1];                 oc[1] = gc[1];
    ou[2] = 2.f * gu[2] - gu[0];   oc[2] = 2.f * gc[2] - gc[0];
    ou[3] = gu[3];                 oc[3] = gc[3];
    ou[4] = 2.f * gu[4] - gu[1];   oc[4] = 2.f * gc[4] - gc[1];
    ou[5] = gu[4];                 oc[5] = gc[4];
    ou[6] = 2.f * gu[5] - gu[3];   oc[6] = 2.f * gc[5] - gc[3];
    #pragma unroll
    for (int m = 0; m < M_OUT; m++) {
        float u = 1.f / (1.f + expf(-(ou[m] + bu)));
        int r = f * M_OUT + m;
        float h = __ldg(hx + (size_t)r * U_DIM + j);
        out[(size_t)r * U_DIM + j] = u * h + (1.f - u) * tanhf(oc[m] + bc);
    }
}

// ---------------- launcher ----------------
extern "C" void kernel_launch(void* const* d_in, const int* in_sizes, int n_in,
                              void* d_out, int out_size) {
    const float* inputs   = (const float*)d_in[0];
    const float* hx       = (const float*)d_in[1];
    const float* w_ru     = (const float*)d_in[2];
    const float* b_ru     = (const float*)d_in[3];
    const float* w_c      = (const float*)d_in[4];
    const float* b_c      = (const float*)d_in[5];
    const float* lap_vals = (const float*)d_in[6];
    const float* rw_vals  = (const float*)d_in[7];
    const int*   lrows    = (const int*)d_in[8];
    const int*   lcols    = (const int*)d_in[9];
    const int*   rrows    = (const int*)d_in[10];
    const int*   rcols    = (const int*)d_in[11];
    float* out = (float*)d_out;

    const int TB = 256;
    const int gE4 = (NNZ / 4 + TB - 1) / TB;
    const int gSp = N_NODES / 16;  // 3125 exact

    // CSR build
    zero2<<<(N_NODES + TB - 1) / TB, TB>>>();
    hist2<<<dim3(gE4, 2), TB>>>(lrows, rrows);
    scan2<<<2, 1024>>>();
    scatter2<<<dim3(gE4, 2), TB>>>(lrows, lcols, lap_vals, rrows, rcols, rw_vals);

    // x0 transpose + weight conversion
    prep<<<(N_NODES * 192 + TB - 1) / TB, TB>>>(inputs, w_ru, w_c);

    // SpMM chain: t1 = L x0; {t2 = L t1, t3 = R t1}; t5 = R t3; t6 = R t5
    spmm_w<<<gSp, 256>>>(0, 0, 1);
    spmm_dual<<<dim3(gSp, 2), 256>>>();
    spmm_w<<<gSp, 256>>>(1, 3, 4);
    spmm_w<<<gSp, 256>>>(1, 4, 5);

    // tensor-core GEMM over 6 matrices + fused combos/epilogue
    gemm_h<<<dim3(KSPLIT, M6), 256>>>();
    finish<<<(F * U_DIM + TB - 1) / TB, TB>>>(hx, b_ru, b_c, out);
}

// round 11
// speedup vs baseline: 1.0237x; 1.0237x over previous
#include <cuda_runtime.h>
#include <cuda_fp16.h>
#include <cstdint>

#define N_NODES 50000
#define NNZ     1600000
#define F       128        // D*B
#define M6      6          // stored matrices: x0,t1,t2,t3,t5,t6
#define M_OUT   7
#define U_DIM   64
#define KSPLIT  24
#define KCH     2112       // 24*2112 = 50688 >= 50000
#define GSTEPS  (KCH / 32) // 66

typedef unsigned int u32;

// ---------------- device scratch (static, no allocation; 16B-aligned for vector casts) ----------------
__device__ __align__(16) __half g_xh[(size_t)M6 * N_NODES * F];       // base matrices in fp16
__device__ __align__(16) __half g_wh[(size_t)N_NODES * F];            // [n][j]: j<64 -> w_ru[:,64+j], j>=64 -> w_c[:,j-64]
__device__ __align__(16) int2   g_csr[2][NNZ];                        // {col, val_bits}
__device__ __align__(16) int    g_rowptr[2][N_NODES + 4];
__device__ __align__(16) int    g_next[2][N_NODES];
__device__ __align__(16) int    g_cnt[2][N_NODES];
__device__ __align__(16) float  g_part[(size_t)KSPLIT * M6 * F * 128];
__device__ __align__(16) float  g_red[(size_t)M6 * F * 128];          // split-K reduced

// ---------------- CSR build ----------------
__global__ void zero2() {
    int i = blockIdx.x * blockDim.x + threadIdx.x;
    if (i < N_NODES) { g_cnt[0][i] = 0; g_cnt[1][i] = 0; }
}

// scalar reads of harness buffers (alignment not guaranteed), 4 edges per thread
__global__ void hist2(const int* __restrict__ lr, const int* __restrict__ rr) {
    int e0 = (blockIdx.x * blockDim.x + threadIdx.x) * 4;
    if (e0 >= NNZ) return;
    int sel = blockIdx.y;
    const int* rows = sel ? rr : lr;
    #pragma unroll
    for (int q = 0; q < 4; q++) {
        atomicAdd(&g_cnt[sel][__ldg(rows + e0 + q)], 1);
    }
}

// one block per sel; exclusive scan of g_cnt[sel] -> g_rowptr[sel] (+ g_next copy)
__global__ void scan2() {
    int sel = blockIdx.x;
    int4* rowptr4 = (int4*)g_rowptr[sel];
    int4* nxt4 = (int4*)g_next[sel];
    const int4* cnt4 = (const int4*)g_cnt[sel];
    __shared__ int warp_sums[32];
    __shared__ int s_carry;
    int tid = threadIdx.x;  // 1024
    if (tid == 0) s_carry = 0;
    __syncthreads();
    const int NQ = N_NODES / 4;  // 12500
    for (int base = 0; base < NQ; base += 1024) {
        int i = base + tid;
        int4 v = (i < NQ) ? cnt4[i] : make_int4(0, 0, 0, 0);
        int s = v.x + v.y + v.z + v.w;
        int x = s;
        #pragma unroll
        for (int o = 1; o < 32; o <<= 1) {
            int y = __shfl_up_sync(0xffffffffu, x, o);
            if ((tid & 31) >= o) x += y;
        }
        if ((tid & 31) == 31) warp_sums[tid >> 5] = x;
        __syncthreads();
        if (tid < 32) {
            int w = warp_sums[tid];
            #pragma unroll
            for (int o = 1; o < 32; o <<= 1) {
                int y = __shfl_up_sync(0xffffffffu, w, o);
                if (tid >= o) w += y;
            }
            warp_sums[tid] = w;
        }
        __syncthreads();
        int warp_off = (tid >= 32) ? warp_sums[(tid >> 5) - 1] : 0;
        int incl = x + warp_off;
        int carry = s_carry;
        if (i < NQ) {
            int p = carry + incl - s;
            int4 o4;
            o4.x = p;
            o4.y = p + v.x;
            o4.z = p + v.x + v.y;
            o4.w = p + v.x + v.y + v.z;
            rowptr4[i] = o4;
            nxt4[i] = o4;
        }
        __syncthreads();
        if (tid == 1023) s_carry = carry + incl;
        __syncthreads();
    }
    if (tid == 0) g_rowptr[sel][N_NODES] = NNZ;
}

// scalar reads; atomic bump cursors; 4 edges per thread
__global__ void scatter2(const int* __restrict__ lr, const int* __restrict__ lc, const float* __restrict__ lv,
                         const int* __restrict__ rr, const int* __restrict__ rc, const float* __restrict__ rv) {
    int e0 = (blockIdx.x * blockDim.x + threadIdx.x) * 4;
    if (e0 >= NNZ) return;
    int sel = blockIdx.y;
    const int* rows = sel ? rr : lr;
    const int* cols = sel ? rc : lc;
    const float* vals = sel ? rv : lv;
    #pragma unroll
    for (int q = 0; q < 4; q++) {
        int e = e0 + q;
        int r = __ldg(rows + e);
        int p = atomicAdd(&g_next[sel][r], 1);
        g_csr[sel][p] = make_int2(__ldg(cols + e), __float_as_int(__ldg(vals + e)));
    }
}

// ---------------- fused prep: x0 transpose + merged fp16 weights ----------------
__global__ void prep(const float* __restrict__ inputs,
                     const float* __restrict__ w_ru, const float* __restrict__ w_c) {
    int idx = blockIdx.x * blockDim.x + threadIdx.x;
    if (idx < N_NODES * 64) {
        int b = idx & 63;
        int n = idx >> 6;
        float vx = __ldg(inputs + ((size_t)b * N_NODES + n) * 2);
        float vy = __ldg(inputs + ((size_t)b * N_NODES + n) * 2 + 1);
        g_xh[(size_t)n * F + b] = __float2half_rn(vx);
        g_xh[(size_t)n * F + 64 + b] = __float2half_rn(vy);
    } else {
        int id2 = idx - N_NODES * 64;
        if (id2 >= N_NODES * F) return;
        int n = id2 >> 7, j = id2 & 127;
        float v = (j < 64) ? __ldg(w_ru + (size_t)n * 128 + 64 + j)
                           : __ldg(w_c + (size_t)n * 64 + (j - 64));
        g_wh[id2] = __float2half_rn(v);
    }
}

// ---------------- SpMM: independent half-warp per row, LDG.128 gathers ----------------
// out = S @ x (raw product only; Chebyshev combines deferred to finish)
__device__ __forceinline__ void spmm_body(int mat, int xi, int oi, int row, int lane) {
    int hl = lane & 15;
    u32 hmask = (lane < 16) ? 0x0000ffffu : 0xffff0000u;
    const uint4* xb = (const uint4*)(g_xh + (size_t)xi * N_NODES * F);
    int e0 = __ldg(&g_rowptr[mat][row]);
    int e1 = __ldg(&g_rowptr[mat][row + 1]);
    float ax = 0.f, ay = 0.f, az = 0.f, aw = 0.f, bx = 0.f, by = 0.f, bz = 0.f, bw = 0.f;
    for (int base = e0; base < e1; base += 16) {
        int n = e1 - base;
        if (n > 16) n = 16;
        int colv = 0; float valv = 0.f;
        if (hl < n) {
            int2 cv = __ldg(&g_csr[mat][base + hl]);
            colv = cv.x << 4;    // uint4 index of gathered row start
            valv = __int_as_float(cv.y);
        }
        int k = 0;
        for (; k + 2 <= n; k += 2) {
            int   c0 = __shfl_sync(hmask, colv, k, 16);
            int   c1 = __shfl_sync(hmask, colv, k + 1, 16);
            float v0 = __shfl_sync(hmask, valv, k, 16);
            float v1 = __shfl_sync(hmask, valv, k + 1, 16);
            uint4 p0 = __ldg(xb + c0 + hl);
            uint4 p1 = __ldg(xb + c1 + hl);
            float2 q0 = __half22float2(*(__half2*)&p0.x);
            float2 q1 = __half22float2(*(__half2*)&p0.y);
            float2 q2 = __half22float2(*(__half2*)&p0.z);
            float2 q3 = __half22float2(*(__half2*)&p0.w);
            ax += v0 * q0.x; ay += v0 * q0.y; az += v0 * q1.x; aw += v0 * q1.y;
            bx += v0 * q2.x; by += v0 * q2.y; bz += v0 * q3.x; bw += v0 * q3.y;
            float2 r0 = __half22float2(*(__half2*)&p1.x);
            float2 r1 = __half22float2(*(__half2*)&p1.y);
            float2 r2 = __half22float2(*(__half2*)&p1.z);
            float2 r3 = __half22float2(*(__half2*)&p1.w);
            ax += v1 * r0.x; ay += v1 * r0.y; az += v1 * r1.x; aw += v1 * r1.y;
            bx += v1 * r2.x; by += v1 * r2.y; bz += v1 * r3.x; bw += v1 * r3.y;
        }
        if (k < n) {
            int   c0 = __shfl_sync(hmask, colv, k, 16);
            float v0 = __shfl_sync(hmask, valv, k, 16);
            uint4 p0 = __ldg(xb + c0 + hl);
            float2 q0 = __half22float2(*(__half2*)&p0.x);
            float2 q1 = __half22float2(*(__half2*)&p0.y);
            float2 q2 = __half22float2(*(__half2*)&p0.z);
            float2 q3 = __half22float2(*(__half2*)&p0.w);
            ax += v0 * q0.x; ay += v0 * q0.y; az += v0 * q1.x; aw += v0 * q1.y;
            bx += v0 * q2.x; by += v0 * q2.y; bz += v0 * q3.x; bw += v0 * q3.y;
        }
    }
    __half2 h0 = __floats2half2_rn(ax, ay);
    __half2 h1 = __floats2half2_rn(az, aw);
    __half2 h2 = __floats2half2_rn(bx, by);
    __half2 h3 = __floats2half2_rn(bz, bw);
    uint4 pk; pk.x = *(u32*)&h0; pk.y = *(u32*)&h1; pk.z = *(u32*)&h2; pk.w = *(u32*)&h3;
    ((uint4*)(g_xh + (size_t)oi * N_NODES * F))[(size_t)row * 16 + hl] = pk;
}

// block = 256 threads = 16 half-warps = 16 rows; grid = 3125 exact
__global__ void __launch_bounds__(256) spmm_w(int mat, int xi, int oi) {
    int lane = threadIdx.x & 31;
    int row = (blockIdx.x << 4) + ((threadIdx.x >> 5) << 1) + (lane >> 4);
    spmm_body(mat, xi, oi, row, lane);
}

// combined: y=0 -> t2 = L t1 ; y=1 -> t3 = R t1
__global__ void __launch_bounds__(256) spmm_dual() {
    int lane = threadIdx.x & 31;
    int row = (blockIdx.x << 4) + ((threadIdx.x >> 5) << 1) + (lane >> 4);
    if (blockIdx.y == 0) spmm_body(0, 1, 2, row, lane);
    else                 spmm_body(1, 1, 3, row, lane);
}

// ---------------- tensor-core GEMM, split-K over 6 base matrices ----------------
__global__ void __launch_bounds__(256) gemm_h() {
    __shared__ __align__(16) __half As[32 * 128];
    __shared__ __align__(16) __half Bs[32 * 128];
    int ks = blockIdx.x, m = blockIdx.y;
    const __half* A = g_xh + (size_t)m * N_NODES * F;
    int tid = threadIdx.x, lane = tid & 31, wid = tid >> 5;
    int f0w = (wid >> 1) * 32;
    int j0w = (wid & 1) * 64;
    u32 as_base = (u32)__cvta_generic_to_shared(As);
    u32 bs_base = (u32)__cvta_generic_to_shared(Bs);

    float c[2][8][4];
    #pragma unroll
    for (int a = 0; a < 2; a++)
        #pragma unroll
        for (int b = 0; b < 8; b++)
            #pragma unroll
            for (int d = 0; d < 4; d++) c[a][b][d] = 0.f;

    int n0 = ks * KCH;
    int lk0 = tid >> 4, lcf = tid & 15;
    int lk1 = lk0 + 16;
    int soff0 = lk0 * 128 + ((lcf ^ (lk0 & 7)) << 3);
    int soff1 = lk1 * 128 + ((lcf ^ (lk1 & 7)) << 3);

    uint4 ra0, ra1, rb0, rb1;
    const uint4 zz = make_uint4(0, 0, 0, 0);
    {
        int na = n0 + lk0, nbg = n0 + lk1;
        if (na < N_NODES) {
            ra0 = *(const uint4*)(A + (size_t)na * F + lcf * 8);
            rb0 = *(const uint4*)(g_wh + (size_t)na * F + lcf * 8);
        } else { ra0 = zz; rb0 = zz; }
        if (nbg < N_NODES) {
            ra1 = *(const uint4*)(A + (size_t)nbg * F + lcf * 8);
            rb1 = *(const uint4*)(g_wh + (size_t)nbg * F + lcf * 8);
        } else { ra1 = zz; rb1 = zz; }
    }

    int g = lane >> 3, i = lane & 7;

    for (int s = 0; s < GSTEPS; s++) {
        __syncthreads();
        *(uint4*)(As + soff0) = ra0; *(uint4*)(Bs + soff0) = rb0;
        *(uint4*)(As + soff1) = ra1; *(uint4*)(Bs + soff1) = rb1;
        __syncthreads();
        if (s + 1 < GSTEPS) {
            int nb = n0 + (s + 1) * 32;
            int na = nb + lk0, nbg = nb + lk1;
            if (na < N_NODES) {
                ra0 = *(const uint4*)(A + (size_t)na * F + lcf * 8);
                rb0 = *(const uint4*)(g_wh + (size_t)na * F + lcf * 8);
            } else { ra0 = zz; rb0 = zz; }
            if (nbg < N_NODES) {
                ra1 = *(const uint4*)(A + (size_t)nbg * F + lcf * 8);
                rb1 = *(const uint4*)(g_wh + (size_t)nbg * F + lcf * 8);
            } else { ra1 = zz; rb1 = zz; }
        }
        #pragma unroll
        for (int kk = 0; kk < 32; kk += 16) {
            u32 a[2][4];
            #pragma unroll
            for (int mt = 0; mt < 2; mt++) {
                int fb = f0w + mt * 16;
                int k = kk + ((g >> 1) << 3) + i;
                int cf = (fb >> 3) + (g & 1);
                u32 addr = as_base + (u32)((k * 128 + ((cf ^ (k & 7)) << 3)) * 2);
                asm volatile("ldmatrix.sync.aligned.m8n8.x4.trans.shared.b16 {%0,%1,%2,%3}, [%4];"
                    : "=r"(a[mt][0]), "=r"(a[mt][1]), "=r"(a[mt][2]), "=r"(a[mt][3]) : "r"(addr));
            }
            u32 b[8][2];
            #pragma unroll
            for (int np = 0; np < 4; np++) {
                int nb = j0w + np * 16;
                int k = kk + ((g & 1) << 3) + i;
                int cf = (nb >> 3) + (g >> 1);
                u32 addr = bs_base + (u32)((k * 128 + ((cf ^ (k & 7)) << 3)) * 2);
                asm volatile("ldmatrix.sync.aligned.m8n8.x4.trans.shared.b16 {%0,%1,%2,%3}, [%4];"
                    : "=r"(b[np * 2][0]), "=r"(b[np * 2][1]), "=r"(b[np * 2 + 1][0]), "=r"(b[np * 2 + 1][1])
                    : "r"(addr));
            }
            #pragma unroll
            for (int mt = 0; mt < 2; mt++)
                #pragma unroll
                for (int nt = 0; nt < 8; nt++)
                    asm volatile("mma.sync.aligned.m16n8k16.row.col.f32.f16.f16.f32 "
                        "{%0,%1,%2,%3}, {%4,%5,%6,%7}, {%8,%9}, {%0,%1,%2,%3};"
                        : "+f"(c[mt][nt][0]), "+f"(c[mt][nt][1]), "+f"(c[mt][nt][2]), "+f"(c[mt][nt][3])
                        : "r"(a[mt][0]), "r"(a[mt][1]), "r"(a[mt][2]), "r"(a[mt][3]),
                          "r"(b[nt][0]), "r"(b[nt][1]));
        }
    }

    float* P = g_part + ((size_t)ks * M6 + m) * F * 128;
    int fr = lane >> 2, jc = (lane & 3) * 2;
    #pragma unroll
    for (int mt = 0; mt < 2; mt++)
        #pragma unroll
        for (int nt = 0; nt < 8; nt++) {
            int f = f0w + mt * 16 + fr;
            int j = j0w + nt * 8 + jc;
            *(float2*)(P + (size_t)f * 128 + j) = make_float2(c[mt][nt][0], c[mt][nt][1]);
            *(float2*)(P + (size_t)(f + 8) * 128 + j) = make_float2(c[mt][nt][2], c[mt][nt][3]);
        }
}

// ---------------- split-K reduce: g_part -> g_red (coalesced, 98304 threads) ----------------
__global__ void __launch_bounds__(256) reduce_part() {
    int idx = blockIdx.x * blockDim.x + threadIdx.x;  // < M6*F*128
    float s = 0.f;
    #pragma unroll 4
    for (int ks = 0; ks < KSPLIT; ks++) {
        s += g_part[(size_t)ks * (M6 * F * 128) + idx];
    }
    g_red[idx] = s;
}

// ---------------- Chebyshev combos + bias + GRU epilogue (57344 threads) ----------------
// G_m = g_red[m]; outputs (m=0..6):
//   O0=G0  O1=G1  O2=2G2-G0  O3=G3  O4=2G4-G1  O5=G4  O6=2G5-G3
__global__ void __launch_bounds__(256) finish(const float* __restrict__ hx, const float* __restrict__ b_ru,
                                              const float* __restrict__ b_c, float* __restrict__ out) {
    int idx = blockIdx.x * blockDim.x + threadIdx.x;  // over 7*128*64
    if (idx >= M_OUT * F * U_DIM) return;
    int j = idx & 63;
    int f = (idx >> 6) & 127;
    int m = idx >> 13;
    const int srcm[M_OUT] = {0, 1, 2, 3, 4, 4, 5};
    const int subm[M_OUT] = {-1, -1, 0, -1, 1, -1, 3};
    int sm = srcm[m], bm = subm[m];
    const float* Gs = g_red + (size_t)sm * F * 128 + (size_t)f * 128;
    float su = Gs[j];
    float sc = Gs[64 + j];
    if (bm >= 0) {
        const float* Gb = g_red + (size_t)bm * F * 128 + (size_t)f * 128;
        su = 2.f * su - Gb[j];
        sc = 2.f * sc - Gb[64 + j];
    }
    su += __ldg(b_ru + 64 + j);
    sc += __ldg(b_c + j);
    float u = 1.f / (1.f + expf(-su));
    int r = f * M_OUT + m;
    float h = __ldg(hx + (size_t)r * U_DIM + j);
    out[(size_t)r * U_DIM + j] = u * h + (1.f - u) * tanhf(sc);
}

// ---------------- launcher ----------------
extern "C" void kernel_launch(void* const* d_in, const int* in_sizes, int n_in,
                              void* d_out, int out_size) {
    const float* inputs   = (const float*)d_in[0];
    const float* hx       = (const float*)d_in[1];
    const float* w_ru     = (const float*)d_in[2];
    const float* b_ru     = (const float*)d_in[3];
    const float* w_c      = (const float*)d_in[4];
    const float* b_c      = (const float*)d_in[5];
    const float* lap_vals = (const float*)d_in[6];
    const float* rw_vals  = (const float*)d_in[7];
    const int*   lrows    = (const int*)d_in[8];
    const int*   lcols    = (const int*)d_in[9];
    const int*   rrows    = (const int*)d_in[10];
    const int*   rcols    = (const int*)d_in[11];
    float* out = (float*)d_out;

    const int TB = 256;
    const int gE4 = (NNZ / 4 + TB - 1) / TB;
    const int gSp = N_NODES / 16;  // 3125 exact

    // CSR build
    zero2<<<(N_NODES + TB - 1) / TB, TB>>>();
    hist2<<<dim3(gE4, 2), TB>>>(lrows, rrows);
    scan2<<<2, 1024>>>();
    scatter2<<<dim3(gE4, 2), TB>>>(lrows, lcols, lap_vals, rrows, rcols, rw_vals);

    // x0 transpose + weight conversion
    prep<<<(N_NODES * 192 + TB - 1) / TB, TB>>>(inputs, w_ru, w_c);

    // SpMM chain: t1 = L x0; {t2 = L t1, t3 = R t1}; t5 = R t3; t6 = R t5
    spmm_w<<<gSp, 256>>>(0, 0, 1);
    spmm_dual<<<dim3(gSp, 2), 256>>>();
    spmm_w<<<gSp, 256>>>(1, 3, 4);
    spmm_w<<<gSp, 256>>>(1, 4, 5);

    // tensor-core GEMM over 6 matrices + parallel reduce + fused combos/epilogue
    gemm_h<<<dim3(KSPLIT, M6), 256>>>();
    reduce_part<<<(M6 * F * 128) / TB, TB>>>();
    finish<<<(M_OUT * F * U_DIM + TB - 1) / TB, TB>>>(hx, b_ru, b_c, out);
}

// round 13
// speedup vs baseline: 1.0291x; 1.0053x over previous
#include <cuda_runtime.h>
#include <cuda_fp16.h>
#include <cstdint>

#define N_NODES 50000
#define NNZ     1600000
#define F       128        // D*B
#define M6      6          // stored matrices: x0,t1,t2,t3,t5,t6
#define M_OUT   7
#define U_DIM   64
#define KSPLIT  24
#define KCH     2112       // 24*2112 = 50688 >= 50000
#define GSTEPS  (KCH / 32) // 66

#define GE4     ((NNZ / 4 + 255) / 256)          // 1563 blocks per matrix for edge work
#define GPREP   ((N_NODES * 192 + 255) / 256)    // 37500 blocks for prep work

typedef unsigned int u32;

// ---------------- device scratch (static, no allocation; 16B-aligned for vector casts) ----------------
__device__ __align__(16) __half g_xh[(size_t)M6 * N_NODES * F];       // base matrices in fp16
__device__ __align__(16) __half g_wh[(size_t)N_NODES * F];            // [n][j]: j<64 -> w_ru[:,64+j], j>=64 -> w_c[:,j-64]
__device__ __align__(16) int2   g_csr[2][NNZ];                        // {col, val_bits}
__device__ __align__(16) int    g_rowptr[2][N_NODES + 4];
__device__ __align__(16) int    g_next[2][N_NODES];
__device__ __align__(16) int    g_cnt[2][N_NODES];                    // zero-init at load; re-zeroed by scan2
__device__ __align__(16) float  g_part[(size_t)KSPLIT * M6 * F * 128];
__device__ __align__(16) float  g_red[(size_t)M6 * F * 128];          // split-K reduced

// ---------------- CSR build ----------------
// scalar reads of harness buffers (alignment not guaranteed), 4 edges per thread
__global__ void hist2(const int* __restrict__ lr, const int* __restrict__ rr) {
    int e0 = (blockIdx.x * blockDim.x + threadIdx.x) * 4;
    if (e0 >= NNZ) return;
    int sel = blockIdx.y;
    const int* rows = sel ? rr : lr;
    #pragma unroll
    for (int q = 0; q < 4; q++) {
        atomicAdd(&g_cnt[sel][__ldg(rows + e0 + q)], 1);
    }
}

// one block per sel; exclusive scan of g_cnt[sel] -> g_rowptr[sel] (+ g_next copy)
// ALSO zeroes g_cnt after reading, so the next kernel_launch call starts clean
// (g_cnt is zero-initialized at module load for the first call).
__global__ void scan2() {
    int sel = blockIdx.x;
    int4* rowptr4 = (int4*)g_rowptr[sel];
    int4* nxt4 = (int4*)g_next[sel];
    int4* cnt4 = (int4*)g_cnt[sel];
    __shared__ int warp_sums[32];
    __shared__ int s_carry;
    int tid = threadIdx.x;  // 1024
    if (tid == 0) s_carry = 0;
    __syncthreads();
    const int NQ = N_NODES / 4;  // 12500
    for (int base = 0; base < NQ; base += 1024) {
        int i = base + tid;
        int4 v = (i < NQ) ? cnt4[i] : make_int4(0, 0, 0, 0);
        int s = v.x + v.y + v.z + v.w;
        int x = s;
        #pragma unroll
        for (int o = 1; o < 32; o <<= 1) {
            int y = __shfl_up_sync(0xffffffffu, x, o);
            if ((tid & 31) >= o) x += y;
        }
        if ((tid & 31) == 31) warp_sums[tid >> 5] = x;
        __syncthreads();
        if (tid < 32) {
            int w = warp_sums[tid];
            #pragma unroll
            for (int o = 1; o < 32; o <<= 1) {
                int y = __shfl_up_sync(0xffffffffu, w, o);
                if (tid >= o) w += y;
            }
            warp_sums[tid] = w;
        }
        __syncthreads();
        int warp_off = (tid >= 32) ? warp_sums[(tid >> 5) - 1] : 0;
        int incl = x + warp_off;
        int carry = s_carry;
        if (i < NQ) {
            int p = carry + incl - s;
            int4 o4;
            o4.x = p;
            o4.y = p + v.x;
            o4.z = p + v.x + v.y;
            o4.w = p + v.x + v.y + v.z;
            rowptr4[i] = o4;
            nxt4[i] = o4;
            cnt4[i] = make_int4(0, 0, 0, 0);   // self-clean for next call
        }
        __syncthreads();
        if (tid == 1023) s_carry = carry + incl;
        __syncthreads();
    }
    if (tid == 0) g_rowptr[sel][N_NODES] = NNZ;
}

// ---------------- fused scatter + prep (independent jobs co-scheduled in one launch) ----------------
// blocks [0, 2*GE4): CSR scatter (sel = b / GE4); blocks [2*GE4, 2*GE4+GPREP): x0 transpose + weight cvt
__global__ void __launch_bounds__(256) scatter_prep(
    const int* __restrict__ lr, const int* __restrict__ lc, const float* __restrict__ lv,
    const int* __restrict__ rr, const int* __restrict__ rc, const float* __restrict__ rv,
    const float* __restrict__ inputs, const float* __restrict__ w_ru, const float* __restrict__ w_c) {
    int b = blockIdx.x;
    if (b < 2 * GE4) {
        int sel = (b >= GE4) ? 1 : 0;
        int e0 = ((b - sel * GE4) * blockDim.x + threadIdx.x) * 4;
        if (e0 >= NNZ) return;
        const int* rows = sel ? rr : lr;
        const int* cols = sel ? rc : lc;
        const float* vals = sel ? rv : lv;
        #pragma unroll
        for (int q = 0; q < 4; q++) {
            int e = e0 + q;
            int r = __ldg(rows + e);
            int p = atomicAdd(&g_next[sel][r], 1);
            g_csr[sel][p] = make_int2(__ldg(cols + e), __float_as_int(__ldg(vals + e)));
        }
    } else {
        int idx = (b - 2 * GE4) * blockDim.x + threadIdx.x;
        if (idx < N_NODES * 64) {
            int bb = idx & 63;
            int n = idx >> 6;
            float vx = __ldg(inputs + ((size_t)bb * N_NODES + n) * 2);
            float vy = __ldg(inputs + ((size_t)bb * N_NODES + n) * 2 + 1);
            g_xh[(size_t)n * F + bb] = __float2half_rn(vx);
            g_xh[(size_t)n * F + 64 + bb] = __float2half_rn(vy);
        } else {
            int id2 = idx - N_NODES * 64;
            if (id2 >= N_NODES * F) return;
            int n = id2 >> 7, j = id2 & 127;
            float v = (j < 64) ? __ldg(w_ru + (size_t)n * 128 + 64 + j)
                               : __ldg(w_c + (size_t)n * 64 + (j - 64));
            g_wh[id2] = __float2half_rn(v);
        }
    }
}

// ---------------- SpMM: independent half-warp per row, LDG.128 gathers ----------------
// out = S @ x (raw product only; Chebyshev combines deferred to finish)
__device__ __forceinline__ void spmm_body(int mat, int xi, int oi, int row, int lane) {
    int hl = lane & 15;
    u32 hmask = (lane < 16) ? 0x0000ffffu : 0xffff0000u;
    const uint4* xb = (const uint4*)(g_xh + (size_t)xi * N_NODES * F);
    int e0 = __ldg(&g_rowptr[mat][row]);
    int e1 = __ldg(&g_rowptr[mat][row + 1]);
    float ax = 0.f, ay = 0.f, az = 0.f, aw = 0.f, bx = 0.f, by = 0.f, bz = 0.f, bw = 0.f;
    for (int base = e0; base < e1; base += 16) {
        int n = e1 - base;
        if (n > 16) n = 16;
        int colv = 0; float valv = 0.f;
        if (hl < n) {
            int2 cv = __ldg(&g_csr[mat][base + hl]);
            colv = cv.x << 4;    // uint4 index of gathered row start
            valv = __int_as_float(cv.y);
        }
        int k = 0;
        for (; k + 2 <= n; k += 2) {
            int   c0 = __shfl_sync(hmask, colv, k, 16);
            int   c1 = __shfl_sync(hmask, colv, k + 1, 16);
            float v0 = __shfl_sync(hmask, valv, k, 16);
            float v1 = __shfl_sync(hmask, valv, k + 1, 16);
            uint4 p0 = __ldg(xb + c0 + hl);
            uint4 p1 = __ldg(xb + c1 + hl);
            float2 q0 = __half22float2(*(__half2*)&p0.x);
            float2 q1 = __half22float2(*(__half2*)&p0.y);
            float2 q2 = __half22float2(*(__half2*)&p0.z);
            float2 q3 = __half22float2(*(__half2*)&p0.w);
            ax += v0 * q0.x; ay += v0 * q0.y; az += v0 * q1.x; aw += v0 * q1.y;
            bx += v0 * q2.x; by += v0 * q2.y; bz += v0 * q3.x; bw += v0 * q3.y;
            float2 r0 = __half22float2(*(__half2*)&p1.x);
            float2 r1 = __half22float2(*(__half2*)&p1.y);
            float2 r2 = __half22float2(*(__half2*)&p1.z);
            float2 r3 = __half22float2(*(__half2*)&p1.w);
            ax += v1 * r0.x; ay += v1 * r0.y; az += v1 * r1.x; aw += v1 * r1.y;
            bx += v1 * r2.x; by += v1 * r2.y; bz += v1 * r3.x; bw += v1 * r3.y;
        }
        if (k < n) {
            int   c0 = __shfl_sync(hmask, colv, k, 16);
            float v0 = __shfl_sync(hmask, valv, k, 16);
            uint4 p0 = __ldg(xb + c0 + hl);
            float2 q0 = __half22float2(*(__half2*)&p0.x);
            float2 q1 = __half22float2(*(__half2*)&p0.y);
            float2 q2 = __half22float2(*(__half2*)&p0.z);
            float2 q3 = __half22float2(*(__half2*)&p0.w);
            ax += v0 * q0.x; ay += v0 * q0.y; az += v0 * q1.x; aw += v0 * q1.y;
            bx += v0 * q2.x; by += v0 * q2.y; bz += v0 * q3.x; bw += v0 * q3.y;
        }
    }
    __half2 h0 = __floats2half2_rn(ax, ay);
    __half2 h1 = __floats2half2_rn(az, aw);
    __half2 h2 = __floats2half2_rn(bx, by);
    __half2 h3 = __floats2half2_rn(bz, bw);
    uint4 pk; pk.x = *(u32*)&h0; pk.y = *(u32*)&h1; pk.z = *(u32*)&h2; pk.w = *(u32*)&h3;
    ((uint4*)(g_xh + (size_t)oi * N_NODES * F))[(size_t)row * 16 + hl] = pk;
}

// block = 256 threads = 16 half-warps = 16 rows; grid = 3125 exact
__global__ void __launch_bounds__(256) spmm_w(int mat, int xi, int oi) {
    int lane = threadIdx.x & 31;
    int row = (blockIdx.x << 4) + ((threadIdx.x >> 5) << 1) + (lane >> 4);
    spmm_body(mat, xi, oi, row, lane);
}

// combined: y=0 -> t2 = L t1 ; y=1 -> t3 = R t1
__global__ void __launch_bounds__(256) spmm_dual() {
    int lane = threadIdx.x & 31;
    int row = (blockIdx.x << 4) + ((threadIdx.x >> 5) << 1) + (lane >> 4);
    if (blockIdx.y == 0) spmm_body(0, 1, 2, row, lane);
    else                 spmm_body(1, 1, 3, row, lane);
}

// ---------------- tensor-core GEMM, split-K over 6 base matrices ----------------
__global__ void __launch_bounds__(256) gemm_h() {
    __shared__ __align__(16) __half As[32 * 128];
    __shared__ __align__(16) __half Bs[32 * 128];
    int ks = blockIdx.x, m = blockIdx.y;
    const __half* A = g_xh + (size_t)m * N_NODES * F;
    int tid = threadIdx.x, lane = tid & 31, wid = tid >> 5;
    int f0w = (wid >> 1) * 32;
    int j0w = (wid & 1) * 64;
    u32 as_base = (u32)__cvta_generic_to_shared(As);
    u32 bs_base = (u32)__cvta_generic_to_shared(Bs);

    float c[2][8][4];
    #pragma unroll
    for (int a = 0; a < 2; a++)
        #pragma unroll
        for (int b = 0; b < 8; b++)
            #pragma unroll
            for (int d = 0; d < 4; d++) c[a][b][d] = 0.f;

    int n0 = ks * KCH;
    int lk0 = tid >> 4, lcf = tid & 15;
    int lk1 = lk0 + 16;
    int soff0 = lk0 * 128 + ((lcf ^ (lk0 & 7)) << 3);
    int soff1 = lk1 * 128 + ((lcf ^ (lk1 & 7)) << 3);

    uint4 ra0, ra1, rb0, rb1;
    const uint4 zz = make_uint4(0, 0, 0, 0);
    {
        int na = n0 + lk0, nbg = n0 + lk1;
        if (na < N_NODES) {
            ra0 = *(const uint4*)(A + (size_t)na * F + lcf * 8);
            rb0 = *(const uint4*)(g_wh + (size_t)na * F + lcf * 8);
        } else { ra0 = zz; rb0 = zz; }
        if (nbg < N_NODES) {
            ra1 = *(const uint4*)(A + (size_t)nbg * F + lcf * 8);
            rb1 = *(const uint4*)(g_wh + (size_t)nbg * F + lcf * 8);
        } else { ra1 = zz; rb1 = zz; }
    }

    int g = lane >> 3, i = lane & 7;

    for (int s = 0; s < GSTEPS; s++) {
        __syncthreads();
        *(uint4*)(As + soff0) = ra0; *(uint4*)(Bs + soff0) = rb0;
        *(uint4*)(As + soff1) = ra1; *(uint4*)(Bs + soff1) = rb1;
        __syncthreads();
        if (s + 1 < GSTEPS) {
            int nb = n0 + (s + 1) * 32;
            int na = nb + lk0, nbg = nb + lk1;
            if (na < N_NODES) {
                ra0 = *(const uint4*)(A + (size_t)na * F + lcf * 8);
                rb0 = *(const uint4*)(g_wh + (size_t)na * F + lcf * 8);
            } else { ra0 = zz; rb0 = zz; }
            if (nbg < N_NODES) {
                ra1 = *(const uint4*)(A + (size_t)nbg * F + lcf * 8);
                rb1 = *(const uint4*)(g_wh + (size_t)nbg * F + lcf * 8);
            } else { ra1 = zz; rb1 = zz; }
        }
        #pragma unroll
        for (int kk = 0; kk < 32; kk += 16) {
            u32 a[2][4];
            #pragma unroll
            for (int mt = 0; mt < 2; mt++) {
                int fb = f0w + mt * 16;
                int k = kk + ((g >> 1) << 3) + i;
                int cf = (fb >> 3) + (g & 1);
                u32 addr = as_base + (u32)((k * 128 + ((cf ^ (k & 7)) << 3)) * 2);
                asm volatile("ldmatrix.sync.aligned.m8n8.x4.trans.shared.b16 {%0,%1,%2,%3}, [%4];"
                    : "=r"(a[mt][0]), "=r"(a[mt][1]), "=r"(a[mt][2]), "=r"(a[mt][3]) : "r"(addr));
            }
            u32 b[8][2];
            #pragma unroll
            for (int np = 0; np < 4; np++) {
                int nb = j0w + np * 16;
                int k = kk + ((g & 1) << 3) + i;
                int cf = (nb >> 3) + (g >> 1);
                u32 addr = bs_base + (u32)((k * 128 + ((cf ^ (k & 7)) << 3)) * 2);
                asm volatile("ldmatrix.sync.aligned.m8n8.x4.trans.shared.b16 {%0,%1,%2,%3}, [%4];"
                    : "=r"(b[np * 2][0]), "=r"(b[np * 2][1]), "=r"(b[np * 2 + 1][0]), "=r"(b[np * 2 + 1][1])
                    : "r"(addr));
            }
            #pragma unroll
            for (int mt = 0; mt < 2; mt++)
                #pragma unroll
                for (int nt = 0; nt < 8; nt++)
                    asm volatile("mma.sync.aligned.m16n8k16.row.col.f32.f16.f16.f32 "
                        "{%0,%1,%2,%3}, {%4,%5,%6,%7}, {%8,%9}, {%0,%1,%2,%3};"
                        : "+f"(c[mt][nt][0]), "+f"(c[mt][nt][1]), "+f"(c[mt][nt][2]), "+f"(c[mt][nt][3])
                        : "r"(a[mt][0]), "r"(a[mt][1]), "r"(a[mt][2]), "r"(a[mt][3]),
                          "r"(b[nt][0]), "r"(b[nt][1]));
        }
    }

    float* P = g_part + ((size_t)ks * M6 + m) * F * 128;
    int fr = lane >> 2, jc = (lane & 3) * 2;
    #pragma unroll
    for (int mt = 0; mt < 2; mt++)
        #pragma unroll
        for (int nt = 0; nt < 8; nt++) {
            int f = f0w + mt * 16 + fr;
            int j = j0w + nt * 8 + jc;
            *(float2*)(P + (size_t)f * 128 + j) = make_float2(c[mt][nt][0], c[mt][nt][1]);
            *(float2*)(P + (size_t)(f + 8) * 128 + j) = make_float2(c[mt][nt][2], c[mt][nt][3]);
        }
}

// ---------------- split-K reduce: g_part -> g_red (coalesced, 98304 threads) ----------------
__global__ void __launch_bounds__(256) reduce_part() {
    int idx = blockIdx.x * blockDim.x + threadIdx.x;  // < M6*F*128
    float s = 0.f;
    #pragma unroll 4
    for (int ks = 0; ks < KSPLIT; ks++) {
        s += g_part[(size_t)ks * (M6 * F * 128) + idx];
    }
    g_red[idx] = s;
}

// ---------------- Chebyshev combos + bias + GRU epilogue (57344 threads) ----------------
// G_m = g_red[m]; outputs (m=0..6):
//   O0=G0  O1=G1  O2=2G2-G0  O3=G3  O4=2G4-G1  O5=G4  O6=2G5-G3
__global__ void __launch_bounds__(256) finish(const float* __restrict__ hx, const float* __restrict__ b_ru,
                                              const float* __restrict__ b_c, float* __restrict__ out) {
    int idx = blockIdx.x * blockDim.x + threadIdx.x;  // over 7*128*64
    if (idx >= M_OUT * F * U_DIM) return;
    int j = idx & 63;
    int f = (idx >> 6) & 127;
    int m = idx >> 13;
    const int srcm[M_OUT] = {0, 1, 2, 3, 4, 4, 5};
    const int subm[M_OUT] = {-1, -1, 0, -1, 1, -1, 3};
    int sm = srcm[m], bm = subm[m];
    const float* Gs = g_red + (size_t)sm * F * 128 + (size_t)f * 128;
    float su = Gs[j];
    float sc = Gs[64 + j];
    if (bm >= 0) {
        const float* Gb = g_red + (size_t)bm * F * 128 + (size_t)f * 128;
        su = 2.f * su - Gb[j];
        sc = 2.f * sc - Gb[64 + j];
    }
    su += __ldg(b_ru + 64 + j);
    sc += __ldg(b_c + j);
    float u = 1.f / (1.f + expf(-su));
    int r = f * M_OUT + m;
    float h = __ldg(hx + (size_t)r * U_DIM + j);
    out[(size_t)r * U_DIM + j] = u * h + (1.f - u) * tanhf(sc);
}

// ---------------- launcher ----------------
extern "C" void kernel_launch(void* const* d_in, const int* in_sizes, int n_in,
                              void* d_out, int out_size) {
    const float* inputs   = (const float*)d_in[0];
    const float* hx       = (const float*)d_in[1];
    const float* w_ru     = (const float*)d_in[2];
    const float* b_ru     = (const float*)d_in[3];
    const float* w_c      = (const float*)d_in[4];
    const float* b_c      = (const float*)d_in[5];
    const float* lap_vals = (const float*)d_in[6];
    const float* rw_vals  = (const float*)d_in[7];
    const int*   lrows    = (const int*)d_in[8];
    const int*   lcols    = (const int*)d_in[9];
    const int*   rrows    = (const int*)d_in[10];
    const int*   rcols    = (const int*)d_in[11];
    float* out = (float*)d_out;

    const int TB = 256;
    const int gSp = N_NODES / 16;  // 3125 exact

    // CSR build (g_cnt is clean: zero-init at load, re-zeroed by scan2 each call)
    hist2<<<dim3(GE4, 2), TB>>>(lrows, rrows);
    scan2<<<2, 1024>>>();
    scatter_prep<<<2 * GE4 + GPREP, TB>>>(lrows, lcols, lap_vals, rrows, rcols, rw_vals,
                                          inputs, w_ru, w_c);

    // SpMM chain: t1 = L x0; {t2 = L t1, t3 = R t1}; t5 = R t3; t6 = R t5
    spmm_w<<<gSp, 256>>>(0, 0, 1);
    spmm_dual<<<dim3(gSp, 2), 256>>>();
    spmm_w<<<gSp, 256>>>(1, 3, 4);
    spmm_w<<<gSp, 256>>>(1, 4, 5);

    // tensor-core GEMM over 6 matrices + parallel reduce + fused combos/epilogue
    gemm_h<<<dim3(KSPLIT, M6), 256>>>();
    reduce_part<<<(M6 * F * 128) / TB, TB>>>();
    finish<<<(M_OUT * F * U_DIM + TB - 1) / TB, TB>>>(hx, b_ru, b_c, out);
}

// round 14
// speedup vs baseline: 1.0741x; 1.0437x over previous
#include <cuda_runtime.h>
#include <cuda_fp16.h>
#include <cstdint>

#define N_NODES 50000
#define NNZ     1600000
#define F       128        // D*B
#define M6      6          // stored matrices: x0,t1,t2,t3,t5,t6
#define M_OUT   7
#define U_DIM   64
#define KSPLIT  24
#define KCH     2112       // 24*2112 = 50688 >= 50000
#define GSTEPS  (KCH / 32) // 66

#define GE4     ((NNZ / 4 + 255) / 256)          // 1563 blocks per matrix for edge work
#define GPREP   ((N_NODES * 192 + 255) / 256)    // 37500 blocks for prep work

typedef unsigned int u32;

// ---------------- device scratch (static, no allocation; 16B-aligned for vector casts) ----------------
__device__ __align__(16) __half g_xh[(size_t)M6 * N_NODES * F];       // base matrices in fp16
__device__ __align__(16) __half g_wh[(size_t)N_NODES * F];            // [n][j]: j<64 -> w_ru[:,64+j], j>=64 -> w_c[:,j-64]
__device__ __align__(16) u32    g_csr[2][NNZ];                        // packed: col(16) | half(val)(16)
__device__ __align__(16) int    g_rowptr[2][N_NODES + 4];
__device__ __align__(16) int    g_next[2][N_NODES];
__device__ __align__(16) int    g_cnt[2][N_NODES];                    // zero-init at load; re-zeroed by scan2
__device__ __align__(16) float  g_part[(size_t)KSPLIT * M6 * F * 128];
__device__ __align__(16) float  g_red[(size_t)M6 * F * 128];          // split-K reduced

// ---------------- CSR build ----------------
// scalar reads of harness buffers (alignment not guaranteed), 4 edges per thread
__global__ void hist2(const int* __restrict__ lr, const int* __restrict__ rr) {
    int e0 = (blockIdx.x * blockDim.x + threadIdx.x) * 4;
    if (e0 >= NNZ) return;
    int sel = blockIdx.y;
    const int* rows = sel ? rr : lr;
    #pragma unroll
    for (int q = 0; q < 4; q++) {
        atomicAdd(&g_cnt[sel][__ldg(rows + e0 + q)], 1);
    }
}

// one block per sel; exclusive scan of g_cnt[sel] -> g_rowptr[sel] (+ g_next copy)
// ALSO zeroes g_cnt after reading, so the next kernel_launch call starts clean
// (g_cnt is zero-initialized at module load for the first call).
__global__ void scan2() {
    int sel = blockIdx.x;
    int4* rowptr4 = (int4*)g_rowptr[sel];
    int4* nxt4 = (int4*)g_next[sel];
    int4* cnt4 = (int4*)g_cnt[sel];
    __shared__ int warp_sums[32];
    __shared__ int s_carry;
    int tid = threadIdx.x;  // 1024
    if (tid == 0) s_carry = 0;
    __syncthreads();
    const int NQ = N_NODES / 4;  // 12500
    for (int base = 0; base < NQ; base += 1024) {
        int i = base + tid;
        int4 v = (i < NQ) ? cnt4[i] : make_int4(0, 0, 0, 0);
        int s = v.x + v.y + v.z + v.w;
        int x = s;
        #pragma unroll
        for (int o = 1; o < 32; o <<= 1) {
            int y = __shfl_up_sync(0xffffffffu, x, o);
            if ((tid & 31) >= o) x += y;
        }
        if ((tid & 31) == 31) warp_sums[tid >> 5] = x;
        __syncthreads();
        if (tid < 32) {
            int w = warp_sums[tid];
            #pragma unroll
            for (int o = 1; o < 32; o <<= 1) {
                int y = __shfl_up_sync(0xffffffffu, w, o);
                if (tid >= o) w += y;
            }
            warp_sums[tid] = w;
        }
        __syncthreads();
        int warp_off = (tid >= 32) ? warp_sums[(tid >> 5) - 1] : 0;
        int incl = x + warp_off;
        int carry = s_carry;
        if (i < NQ) {
            int p = carry + incl - s;
            int4 o4;
            o4.x = p;
            o4.y = p + v.x;
            o4.z = p + v.x + v.y;
            o4.w = p + v.x + v.y + v.z;
            rowptr4[i] = o4;
            nxt4[i] = o4;
            cnt4[i] = make_int4(0, 0, 0, 0);   // self-clean for next call
        }
        __syncthreads();
        if (tid == 1023) s_carry = carry + incl;
        __syncthreads();
    }
    if (tid == 0) g_rowptr[sel][N_NODES] = NNZ;
}

// ---------------- fused scatter + prep (independent jobs co-scheduled in one launch) ----------------
// blocks [0, 2*GE4): CSR scatter (sel = b / GE4); blocks [2*GE4, 2*GE4+GPREP): x0 transpose + weight cvt
__global__ void __launch_bounds__(256) scatter_prep(
    const int* __restrict__ lr, const int* __restrict__ lc, const float* __restrict__ lv,
    const int* __restrict__ rr, const int* __restrict__ rc, const float* __restrict__ rv,
    const float* __restrict__ inputs, const float* __restrict__ w_ru, const float* __restrict__ w_c) {
    int b = blockIdx.x;
    if (b < 2 * GE4) {
        int sel = (b >= GE4) ? 1 : 0;
        int e0 = ((b - sel * GE4) * blockDim.x + threadIdx.x) * 4;
        if (e0 >= NNZ) return;
        const int* rows = sel ? rr : lr;
        const int* cols = sel ? rc : lc;
        const float* vals = sel ? rv : lv;
        #pragma unroll
        for (int q = 0; q < 4; q++) {
            int e = e0 + q;
            int r = __ldg(rows + e);
            u32 packed = ((u32)__ldg(cols + e) & 0xffffu)
                       | ((u32)__half_as_ushort(__float2half_rn(__ldg(vals + e))) << 16);
            int p = atomicAdd(&g_next[sel][r], 1);
            g_csr[sel][p] = packed;
        }
    } else {
        int idx = (b - 2 * GE4) * blockDim.x + threadIdx.x;
        if (idx < N_NODES * 64) {
            int bb = idx & 63;
            int n = idx >> 6;
            float vx = __ldg(inputs + ((size_t)bb * N_NODES + n) * 2);
            float vy = __ldg(inputs + ((size_t)bb * N_NODES + n) * 2 + 1);
            g_xh[(size_t)n * F + bb] = __float2half_rn(vx);
            g_xh[(size_t)n * F + 64 + bb] = __float2half_rn(vy);
        } else {
            int id2 = idx - N_NODES * 64;
            if (id2 >= N_NODES * F) return;
            int n = id2 >> 7, j = id2 & 127;
            float v = (j < 64) ? __ldg(w_ru + (size_t)n * 128 + 64 + j)
                               : __ldg(w_c + (size_t)n * 64 + (j - 64));
            g_wh[id2] = __float2half_rn(v);
        }
    }
}

// ---------------- SpMM: independent half-warp per row, HFMA2 inner product ----------------
// packed CSR: one shfl per edge; val broadcast via .H1_H1 selector (__high2half2).
// 4-edge fp16 windows accumulate into fp32; padding edges have val=0 (harmless gather of row 0).
__device__ __forceinline__ void spmm_body(int mat, int xi, int oi, int row, int lane) {
    int hl = lane & 15;
    u32 hmask = (lane < 16) ? 0x0000ffffu : 0xffff0000u;
    const uint4* xb = (const uint4*)(g_xh + (size_t)xi * N_NODES * F);
    int e0 = __ldg(&g_rowptr[mat][row]);
    int e1 = __ldg(&g_rowptr[mat][row + 1]);
    float f0x = 0.f, f0y = 0.f, f1x = 0.f, f1y = 0.f;
    float f2x = 0.f, f2y = 0.f, f3x = 0.f, f3y = 0.f;
    const __half2 hz = __float2half2_rn(0.f);

    int base = e0;
    // full 16-edge chunks, fully unrolled
    for (; base + 16 <= e1; base += 16) {
        u32 pk = __ldg(&g_csr[mat][base + hl]);
        #pragma unroll
        for (int w = 0; w < 4; w++) {
            __half2 a0 = hz, a1 = hz, a2 = hz, a3 = hz;
            #pragma unroll
            for (int k = 0; k < 4; k++) {
                u32 e = __shfl_sync(hmask, pk, w * 4 + k, 16);
                int c = (int)(e & 0xffffu) << 4;
                __half2 ev = *(__half2*)&e;
                __half2 vv = __high2half2(ev);
                uint4 p = __ldg(xb + c + hl);
                a0 = __hfma2(vv, *(__half2*)&p.x, a0);
                a1 = __hfma2(vv, *(__half2*)&p.y, a1);
                a2 = __hfma2(vv, *(__half2*)&p.z, a2);
                a3 = __hfma2(vv, *(__half2*)&p.w, a3);
            }
            float2 t;
            t = __half22float2(a0); f0x += t.x; f0y += t.y;
            t = __half22float2(a1); f1x += t.x; f1y += t.y;
            t = __half22float2(a2); f2x += t.x; f2y += t.y;
            t = __half22float2(a3); f3x += t.x; f3y += t.y;
        }
    }
    // tail chunk (n < 16): padding lanes carry val=0 -> zero contribution
    int n = e1 - base;
    if (n > 0) {
        u32 pk = (hl < n) ? __ldg(&g_csr[mat][base + hl]) : 0u;
        #pragma unroll
        for (int w = 0; w < 4; w++) {
            if (w * 4 >= n) break;
            __half2 a0 = hz, a1 = hz, a2 = hz, a3 = hz;
            #pragma unroll
            for (int k = 0; k < 4; k++) {
                u32 e = __shfl_sync(hmask, pk, w * 4 + k, 16);
                int c = (int)(e & 0xffffu) << 4;
                __half2 ev = *(__half2*)&e;
                __half2 vv = __high2half2(ev);
                uint4 p = __ldg(xb + c + hl);
                a0 = __hfma2(vv, *(__half2*)&p.x, a0);
                a1 = __hfma2(vv, *(__half2*)&p.y, a1);
                a2 = __hfma2(vv, *(__half2*)&p.z, a2);
                a3 = __hfma2(vv, *(__half2*)&p.w, a3);
            }
            float2 t;
            t = __half22float2(a0); f0x += t.x; f0y += t.y;
            t = __half22float2(a1); f1x += t.x; f1y += t.y;
            t = __half22float2(a2); f2x += t.x; f2y += t.y;
            t = __half22float2(a3); f3x += t.x; f3y += t.y;
        }
    }

    __half2 h0 = __floats2half2_rn(f0x, f0y);
    __half2 h1 = __floats2half2_rn(f1x, f1y);
    __half2 h2 = __floats2half2_rn(f2x, f2y);
    __half2 h3 = __floats2half2_rn(f3x, f3y);
    uint4 pk2; pk2.x = *(u32*)&h0; pk2.y = *(u32*)&h1; pk2.z = *(u32*)&h2; pk2.w = *(u32*)&h3;
    ((uint4*)(g_xh + (size_t)oi * N_NODES * F))[(size_t)row * 16 + hl] = pk2;
}

// block = 256 threads = 16 half-warps = 16 rows; grid = 3125 exact
__global__ void __launch_bounds__(256) spmm_w(int mat, int xi, int oi) {
    int lane = threadIdx.x & 31;
    int row = (blockIdx.x << 4) + ((threadIdx.x >> 5) << 1) + (lane >> 4);
    spmm_body(mat, xi, oi, row, lane);
}

// combined: y=0 -> t2 = L t1 ; y=1 -> t3 = R t1
__global__ void __launch_bounds__(256) spmm_dual() {
    int lane = threadIdx.x & 31;
    int row = (blockIdx.x << 4) + ((threadIdx.x >> 5) << 1) + (lane >> 4);
    if (blockIdx.y == 0) spmm_body(0, 1, 2, row, lane);
    else                 spmm_body(1, 1, 3, row, lane);
}

// ---------------- tensor-core GEMM, split-K over 6 base matrices ----------------
__global__ void __launch_bounds__(256) gemm_h() {
    __shared__ __align__(16) __half As[32 * 128];
    __shared__ __align__(16) __half Bs[32 * 128];
    int ks = blockIdx.x, m = blockIdx.y;
    const __half* A = g_xh + (size_t)m * N_NODES * F;
    int tid = threadIdx.x, lane = tid & 31, wid = tid >> 5;
    int f0w = (wid >> 1) * 32;
    int j0w = (wid & 1) * 64;
    u32 as_base = (u32)__cvta_generic_to_shared(As);
    u32 bs_base = (u32)__cvta_generic_to_shared(Bs);

    float c[2][8][4];
    #pragma unroll
    for (int a = 0; a < 2; a++)
        #pragma unroll
        for (int b = 0; b < 8; b++)
            #pragma unroll
            for (int d = 0; d < 4; d++) c[a][b][d] = 0.f;

    int n0 = ks * KCH;
    int lk0 = tid >> 4, lcf = tid & 15;
    int lk1 = lk0 + 16;
    int soff0 = lk0 * 128 + ((lcf ^ (lk0 & 7)) << 3);
    int soff1 = lk1 * 128 + ((lcf ^ (lk1 & 7)) << 3);

    uint4 ra0, ra1, rb0, rb1;
    const uint4 zz = make_uint4(0, 0, 0, 0);
    {
        int na = n0 + lk0, nbg = n0 + lk1;
        if (na < N_NODES) {
            ra0 = *(const uint4*)(A + (size_t)na * F + lcf * 8);
            rb0 = *(const uint4*)(g_wh + (size_t)na * F + lcf * 8);
        } else { ra0 = zz; rb0 = zz; }
        if (nbg < N_NODES) {
            ra1 = *(const uint4*)(A + (size_t)nbg * F + lcf * 8);
            rb1 = *(const uint4*)(g_wh + (size_t)nbg * F + lcf * 8);
        } else { ra1 = zz; rb1 = zz; }
    }

    int g = lane >> 3, i = lane & 7;

    for (int s = 0; s < GSTEPS; s++) {
        __syncthreads();
        *(uint4*)(As + soff0) = ra0; *(uint4*)(Bs + soff0) = rb0;
        *(uint4*)(As + soff1) = ra1; *(uint4*)(Bs + soff1) = rb1;
        __syncthreads();
        if (s + 1 < GSTEPS) {
            int nb = n0 + (s + 1) * 32;
            int na = nb + lk0, nbg = nb + lk1;
            if (na < N_NODES) {
                ra0 = *(const uint4*)(A + (size_t)na * F + lcf * 8);
                rb0 = *(const uint4*)(g_wh + (size_t)na * F + lcf * 8);
            } else { ra0 = zz; rb0 = zz; }
            if (nbg < N_NODES) {
                ra1 = *(const uint4*)(A + (size_t)nbg * F + lcf * 8);
                rb1 = *(const uint4*)(g_wh + (size_t)nbg * F + lcf * 8);
            } else { ra1 = zz; rb1 = zz; }
        }
        #pragma unroll
        for (int kk = 0; kk < 32; kk += 16) {
            u32 a[2][4];
            #pragma unroll
            for (int mt = 0; mt < 2; mt++) {
                int fb = f0w + mt * 16;
                int k = kk + ((g >> 1) << 3) + i;
                int cf = (fb >> 3) + (g & 1);
                u32 addr = as_base + (u32)((k * 128 + ((cf ^ (k & 7)) << 3)) * 2);
                asm volatile("ldmatrix.sync.aligned.m8n8.x4.trans.shared.b16 {%0,%1,%2,%3}, [%4];"
                    : "=r"(a[mt][0]), "=r"(a[mt][1]), "=r"(a[mt][2]), "=r"(a[mt][3]) : "r"(addr));
            }
            u32 b[8][2];
            #pragma unroll
            for (int np = 0; np < 4; np++) {
                int nb = j0w + np * 16;
                int k = kk + ((g & 1) << 3) + i;
                int cf = (nb >> 3) + (g >> 1);
                u32 addr = bs_base + (u32)((k * 128 + ((cf ^ (k & 7)) << 3)) * 2);
                asm volatile("ldmatrix.sync.aligned.m8n8.x4.trans.shared.b16 {%0,%1,%2,%3}, [%4];"
                    : "=r"(b[np * 2][0]), "=r"(b[np * 2][1]), "=r"(b[np * 2 + 1][0]), "=r"(b[np * 2 + 1][1])
                    : "r"(addr));
            }
            #pragma unroll
            for (int mt = 0; mt < 2; mt++)
                #pragma unroll
                for (int nt = 0; nt < 8; nt++)
                    asm volatile("mma.sync.aligned.m16n8k16.row.col.f32.f16.f16.f32 "
                        "{%0,%1,%2,%3}, {%4,%5,%6,%7}, {%8,%9}, {%0,%1,%2,%3};"
                        : "+f"(c[mt][nt][0]), "+f"(c[mt][nt][1]), "+f"(c[mt][nt][2]), "+f"(c[mt][nt][3])
                        : "r"(a[mt][0]), "r"(a[mt][1]), "r"(a[mt][2]), "r"(a[mt][3]),
                          "r"(b[nt][0]), "r"(b[nt][1]));
        }
    }

    float* P = g_part + ((size_t)ks * M6 + m) * F * 128;
    int fr = lane >> 2, jc = (lane & 3) * 2;
    #pragma unroll
    for (int mt = 0; mt < 2; mt++)
        #pragma unroll
        for (int nt = 0; nt < 8; nt++) {
            int f = f0w + mt * 16 + fr;
            int j = j0w + nt * 8 + jc;
            *(float2*)(P + (size_t)f * 128 + j) = make_float2(c[mt][nt][0], c[mt][nt][1]);
            *(float2*)(P + (size_t)(f + 8) * 128 + j) = make_float2(c[mt][nt][2], c[mt][nt][3]);
        }
}

// ---------------- split-K reduce: g_part -> g_red (coalesced, 98304 threads) ----------------
__global__ void __launch_bounds__(256) reduce_part() {
    int idx = blockIdx.x * blockDim.x + threadIdx.x;  // < M6*F*128
    float s = 0.f;
    #pragma unroll 4
    for (int ks = 0; ks < KSPLIT; ks++) {
        s += g_part[(size_t)ks * (M6 * F * 128) + idx];
    }
    g_red[idx] = s;
}

// ---------------- Chebyshev combos + bias + GRU epilogue (57344 threads) ----------------
// G_m = g_red[m]; outputs (m=0..6):
//   O0=G0  O1=G1  O2=2G2-G0  O3=G3  O4=2G4-G1  O5=G4  O6=2G5-G3
__global__ void __launch_bounds__(256) finish(const float* __restrict__ hx, const float* __restrict__ b_ru,
                                              const float* __restrict__ b_c, float* __restrict__ out) {
    int idx = blockIdx.x * blockDim.x + threadIdx.x;  // over 7*128*64
    if (idx >= M_OUT * F * U_DIM) return;
    int j = idx & 63;
    int f = (idx >> 6) & 127;
    int m = idx >> 13;
    const int srcm[M_OUT] = {0, 1, 2, 3, 4, 4, 5};
    const int subm[M_OUT] = {-1, -1, 0, -1, 1, -1, 3};
    int sm = srcm[m], bm = subm[m];
    const float* Gs = g_red + (size_t)sm * F * 128 + (size_t)f * 128;
    float su = Gs[j];
    float sc = Gs[64 + j];
    if (bm >= 0) {
        const float* Gb = g_red + (size_t)bm * F * 128 + (size_t)f * 128;
        su = 2.f * su - Gb[j];
        sc = 2.f * sc - Gb[64 + j];
    }
    su += __ldg(b_ru + 64 + j);
    sc += __ldg(b_c + j);
    float u = 1.f / (1.f + expf(-su));
    int r = f * M_OUT + m;
    float h = __ldg(hx + (size_t)r * U_DIM + j);
    out[(size_t)r * U_DIM + j] = u * h + (1.f - u) * tanhf(sc);
}

// ---------------- launcher ----------------
extern "C" void kernel_launch(void* const* d_in, const int* in_sizes, int n_in,
                              void* d_out, int out_size) {
    const float* inputs   = (const float*)d_in[0];
    const float* hx       = (const float*)d_in[1];
    const float* w_ru     = (const float*)d_in[2];
    const float* b_ru     = (const float*)d_in[3];
    const float* w_c      = (const float*)d_in[4];
    const float* b_c      = (const float*)d_in[5];
    const float* lap_vals = (const float*)d_in[6];
    const float* rw_vals  = (const float*)d_in[7];
    const int*   lrows    = (const int*)d_in[8];
    const int*   lcols    = (const int*)d_in[9];
    const int*   rrows    = (const int*)d_in[10];
    const int*   rcols    = (const int*)d_in[11];
    float* out = (float*)d_out;

    const int TB = 256;
    const int gSp = N_NODES / 16;  // 3125 exact

    // CSR build (g_cnt is clean: zero-init at load, re-zeroed by scan2 each call)
    hist2<<<dim3(GE4, 2), TB>>>(lrows, rrows);
    scan2<<<2, 1024>>>();
    scatter_prep<<<2 * GE4 + GPREP, TB>>>(lrows, lcols, lap_vals, rrows, rcols, rw_vals,
                                          inputs, w_ru, w_c);

    // SpMM chain: t1 = L x0; {t2 = L t1, t3 = R t1}; t5 = R t3; t6 = R t5
    spmm_w<<<gSp, 256>>>(0, 0, 1);
    spmm_dual<<<dim3(gSp, 2), 256>>>();
    spmm_w<<<gSp, 256>>>(1, 3, 4);
    spmm_w<<<gSp, 256>>>(1, 4, 5);

    // tensor-core GEMM over 6 matrices + parallel reduce + fused combos/epilogue
    gemm_h<<<dim3(KSPLIT, M6), 256>>>();
    reduce_part<<<(M6 * F * 128) / TB, TB>>>();
    finish<<<(M_OUT * F * U_DIM + TB - 1) / TB, TB>>>(hx, b_ru, b_c, out);
}

// round 15
// speedup vs baseline: 1.0869x; 1.0119x over previous
#include <cuda_runtime.h>
#include <cuda_fp16.h>
#include <cstdint>

#define N_NODES 50000
#define NNZ     1600000
#define F       128        // D*B
#define M6      6          // stored matrices: x0,t1,t2,t3,t5,t6
#define M_OUT   7
#define U_DIM   64
#define KSPLIT  24
#define KCH     2112       // 24*2112 = 50688 >= 50000
#define GSTEPS  (KCH / 32) // 66

#define GE4     ((NNZ / 4 + 255) / 256)          // 1563 blocks per matrix for edge work
#define GPREP   ((N_NODES * 192 + 255) / 256)    // 37500 blocks for prep work

typedef unsigned int u32;

// ---------------- device scratch (static, no allocation; 16B-aligned for vector casts) ----------------
__device__ __align__(16) __half g_xh[(size_t)M6 * N_NODES * F];       // base matrices in fp16
__device__ __align__(16) __half g_wh[(size_t)N_NODES * F];            // [n][j]: j<64 -> w_ru[:,64+j], j>=64 -> w_c[:,j-64]
__device__ __align__(16) u32    g_csr[2][NNZ];                        // packed: col(16) | half(val)(16)
__device__ __align__(16) int    g_rowptr[2][N_NODES + 4];
__device__ __align__(16) int    g_next[2][N_NODES];
__device__ __align__(16) int    g_cnt[2][N_NODES];                    // zero-init at load; re-zeroed by scan2
__device__ __align__(16) float  g_part[(size_t)KSPLIT * M6 * F * 128];
__device__ __align__(16) float  g_red[(size_t)M6 * F * 128];          // split-K reduced

// ---------------- CSR build ----------------
// scalar reads of harness buffers (alignment not guaranteed), 4 edges per thread
__global__ void hist2(const int* __restrict__ lr, const int* __restrict__ rr) {
    int e0 = (blockIdx.x * blockDim.x + threadIdx.x) * 4;
    if (e0 >= NNZ) return;
    int sel = blockIdx.y;
    const int* rows = sel ? rr : lr;
    #pragma unroll
    for (int q = 0; q < 4; q++) {
        atomicAdd(&g_cnt[sel][__ldg(rows + e0 + q)], 1);
    }
}

// one block per sel; exclusive scan of g_cnt[sel] -> g_rowptr[sel] (+ g_next copy)
// ALSO zeroes g_cnt after reading, so the next kernel_launch call starts clean
// (g_cnt is zero-initialized at module load for the first call).
__global__ void scan2() {
    int sel = blockIdx.x;
    int4* rowptr4 = (int4*)g_rowptr[sel];
    int4* nxt4 = (int4*)g_next[sel];
    int4* cnt4 = (int4*)g_cnt[sel];
    __shared__ int warp_sums[32];
    __shared__ int s_carry;
    int tid = threadIdx.x;  // 1024
    if (tid == 0) s_carry = 0;
    __syncthreads();
    const int NQ = N_NODES / 4;  // 12500
    for (int base = 0; base < NQ; base += 1024) {
        int i = base + tid;
        int4 v = (i < NQ) ? cnt4[i] : make_int4(0, 0, 0, 0);
        int s = v.x + v.y + v.z + v.w;
        int x = s;
        #pragma unroll
        for (int o = 1; o < 32; o <<= 1) {
            int y = __shfl_up_sync(0xffffffffu, x, o);
            if ((tid & 31) >= o) x += y;
        }
        if ((tid & 31) == 31) warp_sums[tid >> 5] = x;
        __syncthreads();
        if (tid < 32) {
            int w = warp_sums[tid];
            #pragma unroll
            for (int o = 1; o < 32; o <<= 1) {
                int y = __shfl_up_sync(0xffffffffu, w, o);
                if (tid >= o) w += y;
            }
            warp_sums[tid] = w;
        }
        __syncthreads();
        int warp_off = (tid >= 32) ? warp_sums[(tid >> 5) - 1] : 0;
        int incl = x + warp_off;
        int carry = s_carry;
        if (i < NQ) {
            int p = carry + incl - s;
            int4 o4;
            o4.x = p;
            o4.y = p + v.x;
            o4.z = p + v.x + v.y;
            o4.w = p + v.x + v.y + v.z;
            rowptr4[i] = o4;
            nxt4[i] = o4;
            cnt4[i] = make_int4(0, 0, 0, 0);   // self-clean for next call
        }
        __syncthreads();
        if (tid == 1023) s_carry = carry + incl;
        __syncthreads();
    }
    if (tid == 0) g_rowptr[sel][N_NODES] = NNZ;
}

// ---------------- fused scatter + prep (independent jobs co-scheduled in one launch) ----------------
// blocks [0, 2*GE4): CSR scatter (sel = b / GE4); blocks [2*GE4, 2*GE4+GPREP): x0 transpose + weight cvt
__global__ void __launch_bounds__(256) scatter_prep(
    const int* __restrict__ lr, const int* __restrict__ lc, const float* __restrict__ lv,
    const int* __restrict__ rr, const int* __restrict__ rc, const float* __restrict__ rv,
    const float* __restrict__ inputs, const float* __restrict__ w_ru, const float* __restrict__ w_c) {
    int b = blockIdx.x;
    if (b < 2 * GE4) {
        int sel = (b >= GE4) ? 1 : 0;
        int e0 = ((b - sel * GE4) * blockDim.x + threadIdx.x) * 4;
        if (e0 >= NNZ) return;
        const int* rows = sel ? rr : lr;
        const int* cols = sel ? rc : lc;
        const float* vals = sel ? rv : lv;
        #pragma unroll
        for (int q = 0; q < 4; q++) {
            int e = e0 + q;
            int r = __ldg(rows + e);
            u32 packed = ((u32)__ldg(cols + e) & 0xffffu)
                       | ((u32)__half_as_ushort(__float2half_rn(__ldg(vals + e))) << 16);
            int p = atomicAdd(&g_next[sel][r], 1);
            g_csr[sel][p] = packed;
        }
    } else {
        int idx = (b - 2 * GE4) * blockDim.x + threadIdx.x;
        if (idx < N_NODES * 64) {
            int bb = idx & 63;
            int n = idx >> 6;
            float vx = __ldg(inputs + ((size_t)bb * N_NODES + n) * 2);
            float vy = __ldg(inputs + ((size_t)bb * N_NODES + n) * 2 + 1);
            g_xh[(size_t)n * F + bb] = __float2half_rn(vx);
            g_xh[(size_t)n * F + 64 + bb] = __float2half_rn(vy);
        } else {
            int id2 = idx - N_NODES * 64;
            if (id2 >= N_NODES * F) return;
            int n = id2 >> 7, j = id2 & 127;
            float v = (j < 64) ? __ldg(w_ru + (size_t)n * 128 + 64 + j)
                               : __ldg(w_c + (size_t)n * 64 + (j - 64));
            g_wh[id2] = __float2half_rn(v);
        }
    }
}

// ---------------- SpMM: independent half-warp per row, HFMA2 inner product ----------------
// packed CSR: one shfl per edge; val broadcast via .H1_H1 selector (__high2half2).
// 4-edge fp16 windows accumulate into fp32; padding edges have val=0 (harmless gather of row 0).
__device__ __forceinline__ void spmm_body(int mat, int xi, int oi, int row, int lane) {
    int hl = lane & 15;
    u32 hmask = (lane < 16) ? 0x0000ffffu : 0xffff0000u;
    const uint4* xb = (const uint4*)(g_xh + (size_t)xi * N_NODES * F);
    int e0 = __ldg(&g_rowptr[mat][row]);
    int e1 = __ldg(&g_rowptr[mat][row + 1]);
    float f0x = 0.f, f0y = 0.f, f1x = 0.f, f1y = 0.f;
    float f2x = 0.f, f2y = 0.f, f3x = 0.f, f3y = 0.f;
    const __half2 hz = __float2half2_rn(0.f);

    int base = e0;
    // full 16-edge chunks, fully unrolled
    for (; base + 16 <= e1; base += 16) {
        u32 pk = __ldg(&g_csr[mat][base + hl]);
        #pragma unroll
        for (int w = 0; w < 4; w++) {
            __half2 a0 = hz, a1 = hz, a2 = hz, a3 = hz;
            #pragma unroll
            for (int k = 0; k < 4; k++) {
                u32 e = __shfl_sync(hmask, pk, w * 4 + k, 16);
                int c = (int)(e & 0xffffu) << 4;
                __half2 ev = *(__half2*)&e;
                __half2 vv = __high2half2(ev);
                uint4 p = __ldg(xb + c + hl);
                a0 = __hfma2(vv, *(__half2*)&p.x, a0);
                a1 = __hfma2(vv, *(__half2*)&p.y, a1);
                a2 = __hfma2(vv, *(__half2*)&p.z, a2);
                a3 = __hfma2(vv, *(__half2*)&p.w, a3);
            }
            float2 t;
            t = __half22float2(a0); f0x += t.x; f0y += t.y;
            t = __half22float2(a1); f1x += t.x; f1y += t.y;
            t = __half22float2(a2); f2x += t.x; f2y += t.y;
            t = __half22float2(a3); f3x += t.x; f3y += t.y;
        }
    }
    // tail chunk (n < 16): padding lanes carry val=0 -> zero contribution
    int n = e1 - base;
    if (n > 0) {
        u32 pk = (hl < n) ? __ldg(&g_csr[mat][base + hl]) : 0u;
        #pragma unroll
        for (int w = 0; w < 4; w++) {
            if (w * 4 >= n) break;
            __half2 a0 = hz, a1 = hz, a2 = hz, a3 = hz;
            #pragma unroll
            for (int k = 0; k < 4; k++) {
                u32 e = __shfl_sync(hmask, pk, w * 4 + k, 16);
                int c = (int)(e & 0xffffu) << 4;
                __half2 ev = *(__half2*)&e;
                __half2 vv = __high2half2(ev);
                uint4 p = __ldg(xb + c + hl);
                a0 = __hfma2(vv, *(__half2*)&p.x, a0);
                a1 = __hfma2(vv, *(__half2*)&p.y, a1);
                a2 = __hfma2(vv, *(__half2*)&p.z, a2);
                a3 = __hfma2(vv, *(__half2*)&p.w, a3);
            }
            float2 t;
            t = __half22float2(a0); f0x += t.x; f0y += t.y;
            t = __half22float2(a1); f1x += t.x; f1y += t.y;
            t = __half22float2(a2); f2x += t.x; f2y += t.y;
            t = __half22float2(a3); f3x += t.x; f3y += t.y;
        }
    }

    __half2 h0 = __floats2half2_rn(f0x, f0y);
    __half2 h1 = __floats2half2_rn(f1x, f1y);
    __half2 h2 = __floats2half2_rn(f2x, f2y);
    __half2 h3 = __floats2half2_rn(f3x, f3y);
    uint4 pk2; pk2.x = *(u32*)&h0; pk2.y = *(u32*)&h1; pk2.z = *(u32*)&h2; pk2.w = *(u32*)&h3;
    ((uint4*)(g_xh + (size_t)oi * N_NODES * F))[(size_t)row * 16 + hl] = pk2;
}

// block = 256 threads = 16 half-warps = 16 rows; grid = 3125 exact
// min 5 blocks/SM -> 51 regs/thread cap -> 40 resident warps (vs 32 at 52 regs)
__global__ void __launch_bounds__(256, 5) spmm_w(int mat, int xi, int oi) {
    int lane = threadIdx.x & 31;
    int row = (blockIdx.x << 4) + ((threadIdx.x >> 5) << 1) + (lane >> 4);
    spmm_body(mat, xi, oi, row, lane);
}

// combined: y=0 -> t2 = L t1 ; y=1 -> t3 = R t1
__global__ void __launch_bounds__(256, 5) spmm_dual() {
    int lane = threadIdx.x & 31;
    int row = (blockIdx.x << 4) + ((threadIdx.x >> 5) << 1) + (lane >> 4);
    if (blockIdx.y == 0) spmm_body(0, 1, 2, row, lane);
    else                 spmm_body(1, 1, 3, row, lane);
}

// ---------------- tensor-core GEMM, split-K over 6 base matrices ----------------
__global__ void __launch_bounds__(256) gemm_h() {
    __shared__ __align__(16) __half As[32 * 128];
    __shared__ __align__(16) __half Bs[32 * 128];
    int ks = blockIdx.x, m = blockIdx.y;
    const __half* A = g_xh + (size_t)m * N_NODES * F;
    int tid = threadIdx.x, lane = tid & 31, wid = tid >> 5;
    int f0w = (wid >> 1) * 32;
    int j0w = (wid & 1) * 64;
    u32 as_base = (u32)__cvta_generic_to_shared(As);
    u32 bs_base = (u32)__cvta_generic_to_shared(Bs);

    float c[2][8][4];
    #pragma unroll
    for (int a = 0; a < 2; a++)
        #pragma unroll
        for (int b = 0; b < 8; b++)
            #pragma unroll
            for (int d = 0; d < 4; d++) c[a][b][d] = 0.f;

    int n0 = ks * KCH;
    int lk0 = tid >> 4, lcf = tid & 15;
    int lk1 = lk0 + 16;
    int soff0 = lk0 * 128 + ((lcf ^ (lk0 & 7)) << 3);
    int soff1 = lk1 * 128 + ((lcf ^ (lk1 & 7)) << 3);

    uint4 ra0, ra1, rb0, rb1;
    const uint4 zz = make_uint4(0, 0, 0, 0);
    {
        int na = n0 + lk0, nbg = n0 + lk1;
        if (na < N_NODES) {
            ra0 = *(const uint4*)(A + (size_t)na * F + lcf * 8);
            rb0 = *(const uint4*)(g_wh + (size_t)na * F + lcf * 8);
        } else { ra0 = zz; rb0 = zz; }
        if (nbg < N_NODES) {
            ra1 = *(const uint4*)(A + (size_t)nbg * F + lcf * 8);
            rb1 = *(const uint4*)(g_wh + (size_t)nbg * F + lcf * 8);
        } else { ra1 = zz; rb1 = zz; }
    }

    int g = lane >> 3, i = lane & 7;

    for (int s = 0; s < GSTEPS; s++) {
        __syncthreads();
        *(uint4*)(As + soff0) = ra0; *(uint4*)(Bs + soff0) = rb0;
        *(uint4*)(As + soff1) = ra1; *(uint4*)(Bs + soff1) = rb1;
        __syncthreads();
        if (s + 1 < GSTEPS) {
            int nb = n0 + (s + 1) * 32;
            int na = nb + lk0, nbg = nb + lk1;
            if (na < N_NODES) {
                ra0 = *(const uint4*)(A + (size_t)na * F + lcf * 8);
                rb0 = *(const uint4*)(g_wh + (size_t)na * F + lcf * 8);
            } else { ra0 = zz; rb0 = zz; }
            if (nbg < N_NODES) {
                ra1 = *(const uint4*)(A + (size_t)nbg * F + lcf * 8);
                rb1 = *(const uint4*)(g_wh + (size_t)nbg * F + lcf * 8);
            } else { ra1 = zz; rb1 = zz; }
        }
        #pragma unroll
        for (int kk = 0; kk < 32; kk += 16) {
            u32 a[2][4];
            #pragma unroll
            for (int mt = 0; mt < 2; mt++) {
                int fb = f0w + mt * 16;
                int k = kk + ((g >> 1) << 3) + i;
                int cf = (fb >> 3) + (g & 1);
                u32 addr = as_base + (u32)((k * 128 + ((cf ^ (k & 7)) << 3)) * 2);
                asm volatile("ldmatrix.sync.aligned.m8n8.x4.trans.shared.b16 {%0,%1,%2,%3}, [%4];"
                    : "=r"(a[mt][0]), "=r"(a[mt][1]), "=r"(a[mt][2]), "=r"(a[mt][3]) : "r"(addr));
            }
            u32 b[8][2];
            #pragma unroll
            for (int np = 0; np < 4; np++) {
                int nb = j0w + np * 16;
                int k = kk + ((g & 1) << 3) + i;
                int cf = (nb >> 3) + (g >> 1);
                u32 addr = bs_base + (u32)((k * 128 + ((cf ^ (k & 7)) << 3)) * 2);
                asm volatile("ldmatrix.sync.aligned.m8n8.x4.trans.shared.b16 {%0,%1,%2,%3}, [%4];"
                    : "=r"(b[np * 2][0]), "=r"(b[np * 2][1]), "=r"(b[np * 2 + 1][0]), "=r"(b[np * 2 + 1][1])
                    : "r"(addr));
            }
            #pragma unroll
            for (int mt = 0; mt < 2; mt++)
                #pragma unroll
                for (int nt = 0; nt < 8; nt++)
                    asm volatile("mma.sync.aligned.m16n8k16.row.col.f32.f16.f16.f32 "
                        "{%0,%1,%2,%3}, {%4,%5,%6,%7}, {%8,%9}, {%0,%1,%2,%3};"
                        : "+f"(c[mt][nt][0]), "+f"(c[mt][nt][1]), "+f"(c[mt][nt][2]), "+f"(c[mt][nt][3])
                        : "r"(a[mt][0]), "r"(a[mt][1]), "r"(a[mt][2]), "r"(a[mt][3]),
                          "r"(b[nt][0]), "r"(b[nt][1]));
        }
    }

    float* P = g_part + ((size_t)ks * M6 + m) * F * 128;
    int fr = lane >> 2, jc = (lane & 3) * 2;
    #pragma unroll
    for (int mt = 0; mt < 2; mt++)
        #pragma unroll
        for (int nt = 0; nt < 8; nt++) {
            int f = f0w + mt * 16 + fr;
            int j = j0w + nt * 8 + jc;
            *(float2*)(P + (size_t)f * 128 + j) = make_float2(c[mt][nt][0], c[mt][nt][1]);
            *(float2*)(P + (size_t)(f + 8) * 128 + j) = make_float2(c[mt][nt][2], c[mt][nt][3]);
        }
}

// ---------------- split-K reduce: g_part -> g_red (coalesced, 98304 threads) ----------------
__global__ void __launch_bounds__(256) reduce_part() {
    int idx = blockIdx.x * blockDim.x + threadIdx.x;  // < M6*F*128
    float s = 0.f;
    #pragma unroll 4
    for (int ks = 0; ks < KSPLIT; ks++) {
        s += g_part[(size_t)ks * (M6 * F * 128) + idx];
    }
    g_red[idx] = s;
}

// ---------------- Chebyshev combos + bias + GRU epilogue (57344 threads) ----------------
// G_m = g_red[m]; outputs (m=0..6):
//   O0=G0  O1=G1  O2=2G2-G0  O3=G3  O4=2G4-G1  O5=G4  O6=2G5-G3
__global__ void __launch_bounds__(256) finish(const float* __restrict__ hx, const float* __restrict__ b_ru,
                                              const float* __restrict__ b_c, float* __restrict__ out) {
    int idx = blockIdx.x * blockDim.x + threadIdx.x;  // over 7*128*64
    if (idx >= M_OUT * F * U_DIM) return;
    int j = idx & 63;
    int f = (idx >> 6) & 127;
    int m = idx >> 13;
    const int srcm[M_OUT] = {0, 1, 2, 3, 4, 4, 5};
    const int subm[M_OUT] = {-1, -1, 0, -1, 1, -1, 3};
    int sm = srcm[m], bm = subm[m];
    const float* Gs = g_red + (size_t)sm * F * 128 + (size_t)f * 128;
    float su = Gs[j];
    float sc = Gs[64 + j];
    if (bm >= 0) {
        const float* Gb = g_red + (size_t)bm * F * 128 + (size_t)f * 128;
        su = 2.f * su - Gb[j];
        sc = 2.f * sc - Gb[64 + j];
    }
    su += __ldg(b_ru + 64 + j);
    sc += __ldg(b_c + j);
    float u = 1.f / (1.f + expf(-su));
    int r = f * M_OUT + m;
    float h = __ldg(hx + (size_t)r * U_DIM + j);
    out[(size_t)r * U_DIM + j] = u * h + (1.f - u) * tanhf(sc);
}

// ---------------- launcher ----------------
extern "C" void kernel_launch(void* const* d_in, const int* in_sizes, int n_in,
                              void* d_out, int out_size) {
    const float* inputs   = (const float*)d_in[0];
    const float* hx       = (const float*)d_in[1];
    const float* w_ru     = (const float*)d_in[2];
    const float* b_ru     = (const float*)d_in[3];
    const float* w_c      = (const float*)d_in[4];
    const float* b_c      = (const float*)d_in[5];
    const float* lap_vals = (const float*)d_in[6];
    const float* rw_vals  = (const float*)d_in[7];
    const int*   lrows    = (const int*)d_in[8];
    const int*   lcols    = (const int*)d_in[9];
    const int*   rrows    = (const int*)d_in[10];
    const int*   rcols    = (const int*)d_in[11];
    float* out = (float*)d_out;

    const int TB = 256;
    const int gSp = N_NODES / 16;  // 3125 exact

    // CSR build (g_cnt is clean: zero-init at load, re-zeroed by scan2 each call)
    hist2<<<dim3(GE4, 2), TB>>>(lrows, rrows);
    scan2<<<2, 1024>>>();
    scatter_prep<<<2 * GE4 + GPREP, TB>>>(lrows, lcols, lap_vals, rrows, rcols, rw_vals,
                                          inputs, w_ru, w_c);

    // SpMM chain: t1 = L x0; {t2 = L t1, t3 = R t1}; t5 = R t3; t6 = R t5
    spmm_w<<<gSp, 256>>>(0, 0, 1);
    spmm_dual<<<dim3(gSp, 2), 256>>>();
    spmm_w<<<gSp, 256>>>(1, 3, 4);
    spmm_w<<<gSp, 256>>>(1, 4, 5);

    // tensor-core GEMM over 6 matrices + parallel reduce + fused combos/epilogue
    gemm_h<<<dim3(KSPLIT, M6), 256>>>();
    reduce_part<<<(M6 * F * 128) / TB, TB>>>();
    finish<<<(M_OUT * F * U_DIM + TB - 1) / TB, TB>>>(hx, b_ru, b_c, out);
}